// round 1
// baseline (speedup 1.0000x reference)
#include <cuda_runtime.h>
#include <math.h>
#include <float.h>

#define MAXN 20000
#define MAXE 150000
#define TOTIN 37
#define C1 512
#define H1 4
#define C2 128

// ---------------- scratch (static device globals; no allocation) ----------------
static __device__ float g_h0[MAXN * TOTIN];
static __device__ float g_xl1[MAXN * C1];
static __device__ float g_xr1[MAXN * C1];
static __device__ float g_h1[MAXN * C1];
static __device__ float g_xl2[MAXN * C2];
static __device__ float g_xr2[MAXN * C2];
static __device__ float g_alpha1[(MAXE + MAXN) * H1];
static __device__ float g_p1[(MAXE + MAXN) * H1];
static __device__ float g_alpha2[MAXE + MAXN];
static __device__ float g_p2[MAXE + MAXN];
static __device__ float g_amax1[MAXN * H1];
static __device__ float g_den1[MAXN * H1];
static __device__ float g_amax2[MAXN];
static __device__ float g_den2[MAXN];
static __device__ float g_easum[MAXN * 2];
static __device__ float g_loopea[MAXN * 2];
static __device__ int   g_deg[MAXN];
static __device__ int   g_rowstart[MAXN + 1];
static __device__ int   g_cursor[MAXN];
static __device__ int   g_elist[MAXE];

// ---------------- helpers ----------------
__device__ __forceinline__ void atomicMaxFloat(float* addr, float val) {
    int* ai = (int*)addr;
    int old = *ai;
    while (__int_as_float(old) < val) {
        int assumed = old;
        old = atomicCAS(ai, assumed, __float_as_int(val));
        if (old == assumed) break;
    }
}

// ---------------- init: per-node counters / maxima ----------------
__global__ void k_init(int N) {
    int i = blockIdx.x * blockDim.x + threadIdx.x;
    if (i >= N) return;
    g_deg[i] = 0;
    g_cursor[i] = 0;
    g_easum[2 * i] = 0.f;
    g_easum[2 * i + 1] = 0.f;
    g_amax2[i] = -FLT_MAX;
    g_den2[i] = 0.f;
#pragma unroll
    for (int h = 0; h < H1; h++) {
        g_amax1[i * H1 + h] = -FLT_MAX;
        g_den1[i * H1 + h] = 0.f;
    }
}

// ---------------- h0 = concat(x, aa_emb[residue_type]) ----------------
__global__ void k_h0(const float* __restrict__ x, const int* __restrict__ rt,
                     const float* __restrict__ aaemb, int N) {
    int i = blockIdx.x * blockDim.x + threadIdx.x;
    if (i >= N * TOTIN) return;
    int n = i / TOTIN, c = i - n * TOTIN;
    g_h0[i] = (c < 5) ? x[n * 5 + c] : aaemb[rt[n] * 32 + (c - 5)];
}

// ---------------- degree + edge-attr sums (for self-loop fill='mean') ----------------
__global__ void k_deg(const int* __restrict__ dst, const float* __restrict__ ea, int E) {
    int e = blockIdx.x * blockDim.x + threadIdx.x;
    if (e >= E) return;
    int d = dst[e];
    atomicAdd(&g_deg[d], 1);
    atomicAdd(&g_easum[2 * d], ea[2 * e]);
    atomicAdd(&g_easum[2 * d + 1], ea[2 * e + 1]);
}

__global__ void k_loopea(int N) {
    int i = blockIdx.x * blockDim.x + threadIdx.x;
    if (i >= N) return;
    float dg = (float)g_deg[i];
    if (dg < 1.f) dg = 1.f;
    g_loopea[2 * i]     = g_easum[2 * i] / dg;
    g_loopea[2 * i + 1] = g_easum[2 * i + 1] / dg;
}

// ---------------- exclusive prefix scan over degrees (single block) ----------------
__global__ void k_scan(int N) {
    __shared__ int partial[1024];
    int t = threadIdx.x;
    int chunk = (N + 1023) / 1024;
    int beg = t * chunk;
    int end = beg + chunk; if (end > N) end = N;
    int s = 0;
    for (int i = beg; i < end; i++) s += g_deg[i];
    partial[t] = s;
    __syncthreads();
    for (int o = 1; o < 1024; o <<= 1) {
        int v = (t >= o) ? partial[t - o] : 0;
        __syncthreads();
        partial[t] += v;
        __syncthreads();
    }
    int run = partial[t] - s;  // exclusive
    for (int i = beg; i < end; i++) {
        g_rowstart[i] = run;
        run += g_deg[i];
    }
    if (t == 1023) g_rowstart[N] = partial[1023];
}

__global__ void k_scatter(const int* __restrict__ dst, int E) {
    int e = blockIdx.x * blockDim.x + threadIdx.x;
    if (e >= E) return;
    int d = dst[e];
    int pos = atomicAdd(&g_cursor[d], 1);
    g_elist[g_rowstart[d] + pos] = e;
}

// ---------------- layer-1 GEMM: [N,37] @ [37,512] ----------------
// block = 16 nodes x 512 cols, 512 threads; h-row tile in smem, W streamed.
__global__ void k_gemm1(const float* __restrict__ W, int sel, int N) {
    float* out = sel ? g_xr1 : g_xl1;
    int n0 = blockIdx.x * 16;
    int col = threadIdx.x;
    __shared__ float hs[16][TOTIN];
    for (int i = threadIdx.x; i < 16 * TOTIN; i += 512) {
        int m = i / TOTIN, k = i - m * TOTIN;
        int n = n0 + m;
        hs[m][k] = (n < N) ? g_h0[n * TOTIN + k] : 0.f;
    }
    __syncthreads();
    float acc[16];
#pragma unroll
    for (int m = 0; m < 16; m++) acc[m] = 0.f;
    for (int k = 0; k < TOTIN; k++) {
        float w = W[k * C1 + col];
#pragma unroll
        for (int m = 0; m < 16; m++) acc[m] = fmaf(hs[m][k], w, acc[m]);
    }
#pragma unroll
    for (int m = 0; m < 16; m++) {
        int n = n0 + m;
        if (n < N) out[n * C1 + col] = acc[m];
    }
}

// ---------------- layer-1 attention logits: warp per edge ----------------
__global__ void k_alpha1(const int* __restrict__ src, const int* __restrict__ dst,
                         const float* __restrict__ ea, const float* __restrict__ W1e,
                         const float* __restrict__ att, int E, int N) {
    int gw = (blockIdx.x * blockDim.x + threadIdx.x) >> 5;
    int lane = threadIdx.x & 31;
    if (gw >= E + N) return;
    int s, d; float e0, e1;
    if (gw < E) { s = src[gw]; d = dst[gw]; e0 = ea[2 * gw]; e1 = ea[2 * gw + 1]; }
    else        { s = d = gw - E; e0 = g_loopea[2 * d]; e1 = g_loopea[2 * d + 1]; }
    const float* xl = &g_xl1[s * C1];
    const float* xr = &g_xr1[d * C1];
    float part[H1];
#pragma unroll
    for (int h = 0; h < H1; h++) {
        float acc = 0.f;
#pragma unroll
        for (int j = 0; j < 4; j++) {
            int c = h * 128 + j * 32 + lane;
            float ep = e0 * W1e[c] + e1 * W1e[C1 + c];
            float z = xl[c] + xr[c] + ep;
            z = (z > 0.f) ? z : 0.2f * z;
            acc = fmaf(att[c], z, acc);
        }
        part[h] = acc;
    }
#pragma unroll
    for (int o = 16; o > 0; o >>= 1) {
#pragma unroll
        for (int h = 0; h < H1; h++)
            part[h] += __shfl_xor_sync(0xffffffffu, part[h], o);
    }
    if (lane == 0) {
#pragma unroll
        for (int h = 0; h < H1; h++) {
            g_alpha1[gw * H1 + h] = part[h];
            atomicMaxFloat(&g_amax1[d * H1 + h], part[h]);
        }
    }
}

// ---------------- layer-1 softmax numerators + denominators ----------------
__global__ void k_p1(const int* __restrict__ dst, int E, int N) {
    int idx = blockIdx.x * blockDim.x + threadIdx.x;
    if (idx >= (E + N) * H1) return;
    int e = idx >> 2, h = idx & 3;
    int d = (e < E) ? dst[e] : (e - E);
    float p = expf(g_alpha1[idx] - g_amax1[d * H1 + h]);
    g_p1[idx] = p;
    atomicAdd(&g_den1[d * H1 + h], p);
}

// ---------------- layer-1 aggregation (CSR) + bias + ELU ----------------
__global__ void k_agg1(const int* __restrict__ src, const float* __restrict__ b1, int E) {
    int d = blockIdx.x;
    int t = threadIdx.x;  // 128 threads; thread t owns channels {h*128+t}
    float acc[H1] = {0.f, 0.f, 0.f, 0.f};
    {   // self loop
        const float* xl = &g_xl1[d * C1];
#pragma unroll
        for (int j = 0; j < H1; j++)
            acc[j] = fmaf(g_p1[(E + d) * H1 + j], xl[j * 128 + t], acc[j]);
    }
    int rs = g_rowstart[d], re = g_rowstart[d + 1];
    for (int i = rs; i < re; i++) {
        int e = g_elist[i];
        const float* xl = &g_xl1[src[e] * C1];
#pragma unroll
        for (int j = 0; j < H1; j++)
            acc[j] = fmaf(g_p1[e * H1 + j], xl[j * 128 + t], acc[j]);
    }
#pragma unroll
    for (int j = 0; j < H1; j++) {
        float v = acc[j] / g_den1[d * H1 + j] + b1[j * 128 + t];
        v = (v > 0.f) ? v : (expf(v) - 1.f);  // ELU
        g_h1[d * C1 + j * 128 + t] = v;
    }
}

// ---------------- layer-2 GEMM: [N,512] @ [512,128], 64x128 tile ----------------
__global__ void k_gemm2(const float* __restrict__ W, int sel, int N) {
    float* out = sel ? g_xr2 : g_xl2;
    __shared__ float As[64][17];
    __shared__ float Bs[16][128];
    int tid = threadIdx.x;
    int tx = tid & 31, ty = tid >> 5;  // ty in [0,8)
    int n0 = blockIdx.x * 64;
    float acc[8][4];
#pragma unroll
    for (int j = 0; j < 8; j++)
#pragma unroll
        for (int i2 = 0; i2 < 4; i2++) acc[j][i2] = 0.f;
    for (int k0 = 0; k0 < C1; k0 += 16) {
        for (int i = tid; i < 64 * 16; i += 256) {
            int m = i >> 4, kk = i & 15;
            int n = n0 + m;
            As[m][kk] = (n < N) ? g_h1[n * C1 + k0 + kk] : 0.f;
        }
        for (int i = tid; i < 16 * 128; i += 256) {
            int kk = i >> 7, c = i & 127;
            Bs[kk][c] = W[(k0 + kk) * C2 + c];
        }
        __syncthreads();
#pragma unroll
        for (int kk = 0; kk < 16; kk++) {
            float a[8], b[4];
#pragma unroll
            for (int j = 0; j < 8; j++) a[j] = As[ty + 8 * j][kk];
#pragma unroll
            for (int i2 = 0; i2 < 4; i2++) b[i2] = Bs[kk][tx + 32 * i2];
#pragma unroll
            for (int j = 0; j < 8; j++)
#pragma unroll
                for (int i2 = 0; i2 < 4; i2++)
                    acc[j][i2] = fmaf(a[j], b[i2], acc[j][i2]);
        }
        __syncthreads();
    }
#pragma unroll
    for (int j = 0; j < 8; j++) {
        int n = n0 + ty + 8 * j;
        if (n < N) {
#pragma unroll
            for (int i2 = 0; i2 < 4; i2++)
                out[n * C2 + tx + 32 * i2] = acc[j][i2];
        }
    }
}

// ---------------- layer-2 attention logits: warp per edge ----------------
__global__ void k_alpha2(const int* __restrict__ src, const int* __restrict__ dst,
                         const float* __restrict__ ea, const float* __restrict__ W2e,
                         const float* __restrict__ att2, int E, int N) {
    int gw = (blockIdx.x * blockDim.x + threadIdx.x) >> 5;
    int lane = threadIdx.x & 31;
    if (gw >= E + N) return;
    int s, d; float e0, e1;
    if (gw < E) { s = src[gw]; d = dst[gw]; e0 = ea[2 * gw]; e1 = ea[2 * gw + 1]; }
    else        { s = d = gw - E; e0 = g_loopea[2 * d]; e1 = g_loopea[2 * d + 1]; }
    const float* xl = &g_xl2[s * C2];
    const float* xr = &g_xr2[d * C2];
    float acc = 0.f;
#pragma unroll
    for (int j = 0; j < 4; j++) {
        int c = j * 32 + lane;
        float ep = e0 * W2e[c] + e1 * W2e[C2 + c];
        float z = xl[c] + xr[c] + ep;
        z = (z > 0.f) ? z : 0.2f * z;
        acc = fmaf(att2[c], z, acc);
    }
#pragma unroll
    for (int o = 16; o > 0; o >>= 1) acc += __shfl_xor_sync(0xffffffffu, acc, o);
    if (lane == 0) {
        g_alpha2[gw] = acc;
        atomicMaxFloat(&g_amax2[d], acc);
    }
}

__global__ void k_p2(const int* __restrict__ dst, int E, int N) {
    int e = blockIdx.x * blockDim.x + threadIdx.x;
    if (e >= E + N) return;
    int d = (e < E) ? dst[e] : (e - E);
    float p = expf(g_alpha2[e] - g_amax2[d]);
    g_p2[e] = p;
    atomicAdd(&g_den2[d], p);
}

// ---------------- layer-2 aggregation + ELU + fused FC ----------------
__global__ void k_agg2(const int* __restrict__ src, const float* __restrict__ b2,
                       const float* __restrict__ Wfc, const float* __restrict__ bfc,
                       float* __restrict__ out, int E) {
    int d = blockIdx.x;
    int t = threadIdx.x;  // 128 threads, 1 channel each
    float acc = g_p2[E + d] * g_xl2[d * C2 + t];  // self loop
    int rs = g_rowstart[d], re = g_rowstart[d + 1];
    for (int i = rs; i < re; i++) {
        int e = g_elist[i];
        acc = fmaf(g_p2[e], g_xl2[src[e] * C2 + t], acc);
    }
    float v = acc / g_den2[d] + b2[t];
    v = (v > 0.f) ? v : (expf(v) - 1.f);  // ELU
    float o0 = v * Wfc[2 * t];
    float o1 = v * Wfc[2 * t + 1];
#pragma unroll
    for (int o = 16; o > 0; o >>= 1) {
        o0 += __shfl_xor_sync(0xffffffffu, o0, o);
        o1 += __shfl_xor_sync(0xffffffffu, o1, o);
    }
    __shared__ float r0[4], r1[4];
    int w = t >> 5;
    if ((t & 31) == 0) { r0[w] = o0; r1[w] = o1; }
    __syncthreads();
    if (t == 0) {
        out[2 * d]     = r0[0] + r0[1] + r0[2] + r0[3] + bfc[0];
        out[2 * d + 1] = r1[0] + r1[1] + r1[2] + r1[3] + bfc[1];
    }
}

// ---------------- launch ----------------
extern "C" void kernel_launch(void* const* d_in, const int* in_sizes, int n_in,
                              void* d_out, int out_size) {
    const float* x    = (const float*)d_in[0];
    const int*   ei   = (const int*)  d_in[1];
    const float* ea   = (const float*)d_in[2];
    const int*   rt   = (const int*)  d_in[3];
    const float* aaem = (const float*)d_in[4];
    const float* W1l  = (const float*)d_in[5];
    const float* W1r  = (const float*)d_in[6];
    const float* W1e  = (const float*)d_in[7];
    const float* att1 = (const float*)d_in[8];
    const float* b1   = (const float*)d_in[9];
    const float* W2l  = (const float*)d_in[10];
    const float* W2r  = (const float*)d_in[11];
    const float* W2e  = (const float*)d_in[12];
    const float* att2 = (const float*)d_in[13];
    const float* b2   = (const float*)d_in[14];
    const float* Wfc  = (const float*)d_in[15];
    const float* bfc  = (const float*)d_in[16];
    float* out = (float*)d_out;

    int N = in_sizes[0] / 5;
    int E = in_sizes[1] / 2;
    if (N > MAXN) N = MAXN;
    if (E > MAXE) E = MAXE;
    const int* src = ei;
    const int* dst = ei + E;

    k_init<<<(N + 255) / 256, 256>>>(N);
    k_h0<<<(N * TOTIN + 255) / 256, 256>>>(x, rt, aaem, N);
    k_deg<<<(E + 255) / 256, 256>>>(dst, ea, E);
    k_loopea<<<(N + 255) / 256, 256>>>(N);
    k_scan<<<1, 1024>>>(N);
    k_scatter<<<(E + 255) / 256, 256>>>(dst, E);

    k_gemm1<<<(N + 15) / 16, 512>>>(W1l, 0, N);
    k_gemm1<<<(N + 15) / 16, 512>>>(W1r, 1, N);

    {
        int nwarp = E + N;
        int blocks = (nwarp * 32 + 255) / 256;
        k_alpha1<<<blocks, 256>>>(src, dst, ea, W1e, att1, E, N);
    }
    k_p1<<<((E + N) * H1 + 255) / 256, 256>>>(dst, E, N);
    k_agg1<<<N, 128>>>(src, b1, E);

    k_gemm2<<<(N + 63) / 64, 256>>>(W2l, 0, N);
    k_gemm2<<<(N + 63) / 64, 256>>>(W2r, 1, N);

    {
        int nwarp = E + N;
        int blocks = (nwarp * 32 + 255) / 256;
        k_alpha2<<<blocks, 256>>>(src, dst, ea, W2e, att2, E, N);
    }
    k_p2<<<(E + N + 255) / 256, 256>>>(dst, E, N);
    k_agg2<<<N, 128>>>(src, b2, Wfc, bfc, out, E);
}

// round 3
// speedup vs baseline: 1.2791x; 1.2791x over previous
#include <cuda_runtime.h>
#include <mma.h>
#include <math.h>
#include <float.h>

using namespace nvcuda;

#define MAXN 20000
#define MAXNP 20032           // padded to multiple of 64 for WMMA tiles
#define MAXE 150000
#define TOTINP 40             // 37 padded to 40 (multiple of 8 for tf32 K)
#define C1 512
#define H1 4
#define C2 128

// ---------------- scratch ----------------
static __device__ float g_h0[MAXNP * TOTINP];
static __device__ float g_xl1[MAXNP * C1];
static __device__ float g_xr1[MAXNP * C1];
static __device__ float g_h1[MAXNP * C1];
static __device__ float g_xl2[MAXNP * C2];
static __device__ float g_xr2[MAXNP * C2];
static __device__ float g_p1[MAXE * H1];     // CSR-sorted per-edge softmax numerators
static __device__ float g_ps1[MAXN * H1];    // self-loop numerators
static __device__ float g_p2[MAXE];
static __device__ float g_ps2[MAXN];
static __device__ float g_den1[MAXN * H1];
static __device__ float g_den2[MAXN];
static __device__ float g_easum[MAXN * 2];
static __device__ float g_loopea[MAXN * 2];
static __device__ int   g_deg[MAXN];
static __device__ int   g_rowstart[MAXN + 1];
static __device__ int   g_cursor[MAXN];
static __device__ int   g_esrc[MAXE];        // src[] permuted into CSR order
static __device__ int   g_epos[MAXE];        // edge -> CSR slot

// ---------------- init ----------------
__global__ void k_init(int N) {
    int i = blockIdx.x * blockDim.x + threadIdx.x;
    if (i >= N) return;
    g_deg[i] = 0;
    g_cursor[i] = 0;
    g_easum[2 * i] = 0.f;
    g_easum[2 * i + 1] = 0.f;
    g_den2[i] = 0.f;
#pragma unroll
    for (int h = 0; h < H1; h++) g_den1[i * H1 + h] = 0.f;
}

// ---------------- h0 = concat(x, aa_emb[residue_type]), padded to 40 ----------------
__global__ void k_h0(const float* __restrict__ x, const int* __restrict__ rt,
                     const float* __restrict__ aaemb, int N) {
    int i = blockIdx.x * blockDim.x + threadIdx.x;
    if (i >= N * TOTINP) return;
    int n = i / TOTINP, c = i - n * TOTINP;
    float v = 0.f;
    if (c < 5) v = x[n * 5 + c];
    else if (c < 37) v = aaemb[rt[n] * 32 + (c - 5)];
    g_h0[i] = v;
}

// ---------------- degree + edge-attr sums ----------------
__global__ void k_deg(const int* __restrict__ dst, const float* __restrict__ ea, int E) {
    int e = blockIdx.x * blockDim.x + threadIdx.x;
    if (e >= E) return;
    int d = dst[e];
    float2 a = ((const float2*)ea)[e];
    atomicAdd(&g_deg[d], 1);
    atomicAdd(&g_easum[2 * d], a.x);
    atomicAdd(&g_easum[2 * d + 1], a.y);
}

// ---------------- prefix scan + self-loop edge-attr mean ----------------
__global__ void k_scan(int N) {
    __shared__ int partial[1024];
    int t = threadIdx.x;
    int chunk = (N + 1023) / 1024;
    int beg = t * chunk;
    int end = beg + chunk; if (end > N) end = N;
    int s = 0;
    for (int i = beg; i < end; i++) s += g_deg[i];
    partial[t] = s;
    __syncthreads();
    for (int o = 1; o < 1024; o <<= 1) {
        int v = (t >= o) ? partial[t - o] : 0;
        __syncthreads();
        partial[t] += v;
        __syncthreads();
    }
    int run = partial[t] - s;
    for (int i = beg; i < end; i++) {
        g_rowstart[i] = run;
        int dg = g_deg[i];
        run += dg;
        float fd = (dg < 1) ? 1.f : (float)dg;
        g_loopea[2 * i]     = g_easum[2 * i] / fd;
        g_loopea[2 * i + 1] = g_easum[2 * i + 1] / fd;
    }
    if (t == 1023) g_rowstart[N] = partial[1023];
}

__global__ void k_scatter(const int* __restrict__ src, const int* __restrict__ dst, int E) {
    int e = blockIdx.x * blockDim.x + threadIdx.x;
    if (e >= E) return;
    int d = dst[e];
    int pos = g_rowstart[d] + atomicAdd(&g_cursor[d], 1);
    g_esrc[pos] = src[e];
    g_epos[e] = pos;
}

// ---------------- layer-1 GEMM (tf32 WMMA): [NP,40] @ [40,512] ----------------
// grid (NP/64, 4, 2), 256 threads. BM=64 BN=128 K=40.
__global__ void __launch_bounds__(256) k_gemm1(const float* __restrict__ Wl,
                                               const float* __restrict__ Wr, int N) {
    const float* W = blockIdx.z ? Wr : Wl;
    float* out = blockIdx.z ? g_xr1 : g_xl1;
    __shared__ float As[64 * 44];
    __shared__ float Bs[40 * 132];
    int tid = threadIdx.x;
    int n0 = blockIdx.x * 64;
    int col0 = blockIdx.y * 128;
    for (int idx = tid; idx < 64 * 40; idx += 256) {
        int r = idx / 40, c = idx - r * 40;
        float v = (n0 + r < N) ? g_h0[(n0 + r) * TOTINP + c] : 0.f;
        As[r * 44 + c] = wmma::__float_to_tf32(v);
    }
    for (int idx = tid; idx < 40 * 128; idx += 256) {
        int r = idx >> 7, c = idx & 127;
        float v = (r < 37) ? W[r * C1 + col0 + c] : 0.f;
        Bs[r * 132 + c] = wmma::__float_to_tf32(v);
    }
    __syncthreads();
    int wid = tid >> 5;
    int wr = wid & 1, wc = wid >> 1;    // 2 x 4 warp grid over 64 x 128
    wmma::fragment<wmma::accumulator, 16, 16, 8, float> acc[2][2];
#pragma unroll
    for (int i = 0; i < 2; i++)
#pragma unroll
        for (int j = 0; j < 2; j++) wmma::fill_fragment(acc[i][j], 0.f);
#pragma unroll
    for (int k0 = 0; k0 < 40; k0 += 8) {
        wmma::fragment<wmma::matrix_a, 16, 16, 8, wmma::precision::tf32, wmma::row_major> a[2];
        wmma::fragment<wmma::matrix_b, 16, 16, 8, wmma::precision::tf32, wmma::row_major> b[2];
#pragma unroll
        for (int i = 0; i < 2; i++)
            wmma::load_matrix_sync(a[i], &As[(wr * 32 + i * 16) * 44 + k0], 44);
#pragma unroll
        for (int j = 0; j < 2; j++)
            wmma::load_matrix_sync(b[j], &Bs[k0 * 132 + wc * 32 + j * 16], 132);
#pragma unroll
        for (int i = 0; i < 2; i++)
#pragma unroll
            for (int j = 0; j < 2; j++)
                wmma::mma_sync(acc[i][j], a[i], b[j], acc[i][j]);
    }
#pragma unroll
    for (int i = 0; i < 2; i++)
#pragma unroll
        for (int j = 0; j < 2; j++)
            wmma::store_matrix_sync(&out[(n0 + wr * 32 + i * 16) * C1 + col0 + wc * 32 + j * 16],
                                    acc[i][j], C1, wmma::mem_row_major);
}

// ---------------- layer-2 GEMM (tf32 WMMA): [NP,512] @ [512,128] ----------------
// grid (NP/64, 1, 2), 256 threads. BM=64 BN=128 BK=32.
__global__ void __launch_bounds__(256) k_gemm2(const float* __restrict__ Wl,
                                               const float* __restrict__ Wr, int N) {
    const float* W = blockIdx.z ? Wr : Wl;
    float* out = blockIdx.z ? g_xr2 : g_xl2;
    __shared__ float As[64 * 36];
    __shared__ float Bs[32 * 132];
    int tid = threadIdx.x;
    int n0 = blockIdx.x * 64;
    int wid = tid >> 5;
    int wr = wid & 1, wc = wid >> 1;
    wmma::fragment<wmma::accumulator, 16, 16, 8, float> acc[2][2];
#pragma unroll
    for (int i = 0; i < 2; i++)
#pragma unroll
        for (int j = 0; j < 2; j++) wmma::fill_fragment(acc[i][j], 0.f);
    for (int k0 = 0; k0 < C1; k0 += 32) {
        for (int idx = tid; idx < 64 * 32; idx += 256) {
            int r = idx >> 5, c = idx & 31;
            float v = (n0 + r < N) ? g_h1[(n0 + r) * C1 + k0 + c] : 0.f;
            As[r * 36 + c] = wmma::__float_to_tf32(v);
        }
        for (int idx = tid; idx < 32 * 128; idx += 256) {
            int r = idx >> 7, c = idx & 127;
            Bs[r * 132 + c] = wmma::__float_to_tf32(W[(k0 + r) * C2 + c]);
        }
        __syncthreads();
#pragma unroll
        for (int kk = 0; kk < 32; kk += 8) {
            wmma::fragment<wmma::matrix_a, 16, 16, 8, wmma::precision::tf32, wmma::row_major> a[2];
            wmma::fragment<wmma::matrix_b, 16, 16, 8, wmma::precision::tf32, wmma::row_major> b[2];
#pragma unroll
            for (int i = 0; i < 2; i++)
                wmma::load_matrix_sync(a[i], &As[(wr * 32 + i * 16) * 36 + kk], 36);
#pragma unroll
            for (int j = 0; j < 2; j++)
                wmma::load_matrix_sync(b[j], &Bs[kk * 132 + wc * 32 + j * 16], 132);
#pragma unroll
            for (int i = 0; i < 2; i++)
#pragma unroll
                for (int j = 0; j < 2; j++)
                    wmma::mma_sync(acc[i][j], a[i], b[j], acc[i][j]);
        }
        __syncthreads();
    }
#pragma unroll
    for (int i = 0; i < 2; i++)
#pragma unroll
        for (int j = 0; j < 2; j++)
            wmma::store_matrix_sync(&out[(n0 + wr * 32 + i * 16) * C2 + wc * 32 + j * 16],
                                    acc[i][j], C2, wmma::mem_row_major);
}

// ---------------- layer-1 attention: warp/edge, fused exp + denom ----------------
__global__ void k_att1(const int* __restrict__ src, const int* __restrict__ dst,
                       const float* __restrict__ ea, const float* __restrict__ W1e,
                       const float* __restrict__ att, int E, int N) {
    int gw = (blockIdx.x * blockDim.x + threadIdx.x) >> 5;
    int lane = threadIdx.x & 31;
    if (gw >= E + N) return;
    int s, d, outIdx; float e0, e1;
    if (gw < E) {
        s = __ldg(src + gw); d = __ldg(dst + gw);
        float2 a2 = __ldg((const float2*)ea + gw);
        e0 = a2.x; e1 = a2.y;
        outIdx = g_epos[gw];
    } else {
        s = d = gw - E;
        e0 = g_loopea[2 * d]; e1 = g_loopea[2 * d + 1];
        outIdx = -1;
    }
    const float4* xl4 = (const float4*)&g_xl1[s * C1];
    const float4* xr4 = (const float4*)&g_xr1[d * C1];
    const float4* w04 = (const float4*)W1e;
    const float4* w14 = (const float4*)(W1e + C1);
    const float4* a4  = (const float4*)att;
    float p0, p1, p2, p3;
    {
        float part[H1];
#pragma unroll
        for (int h = 0; h < H1; h++) {
            int c = h * 32 + lane;
            float4 l = xl4[c], r = xr4[c];
            float4 w0 = __ldg(w04 + c), w1 = __ldg(w14 + c), a = __ldg(a4 + c);
            float zx = l.x + r.x + e0 * w0.x + e1 * w1.x; zx = zx > 0.f ? zx : 0.2f * zx;
            float zy = l.y + r.y + e0 * w0.y + e1 * w1.y; zy = zy > 0.f ? zy : 0.2f * zy;
            float zz = l.z + r.z + e0 * w0.z + e1 * w1.z; zz = zz > 0.f ? zz : 0.2f * zz;
            float zw = l.w + r.w + e0 * w0.w + e1 * w1.w; zw = zw > 0.f ? zw : 0.2f * zw;
            part[h] = a.x * zx + a.y * zy + a.z * zz + a.w * zw;
        }
#pragma unroll
        for (int o = 16; o > 0; o >>= 1) {
#pragma unroll
            for (int h = 0; h < H1; h++)
                part[h] += __shfl_xor_sync(0xffffffffu, part[h], o);
        }
        p0 = part[0]; p1 = part[1]; p2 = part[2]; p3 = part[3];
    }
    if (lane < 4) {
        float al = (lane == 0) ? p0 : (lane == 1) ? p1 : (lane == 2) ? p2 : p3;
        float p = __expf(al);       // logits are O(1): no max-subtraction needed
        if (outIdx >= 0) g_p1[outIdx * H1 + lane] = p;
        else             g_ps1[d * H1 + lane] = p;
        atomicAdd(&g_den1[d * H1 + lane], p);
    }
}

// ---------------- layer-1 aggregation (CSR, float4) + bias + ELU ----------------
__global__ void k_agg1(const float* __restrict__ b1, int N) {
    int d = blockIdx.x;
    int t = threadIdx.x;          // 128 threads, float4 each (channels 4t..4t+3)
    int h = t >> 5;
    float4 acc;
    {
        float p = g_ps1[d * H1 + h];
        float4 v = ((const float4*)&g_xl1[d * C1])[t];
        acc.x = p * v.x; acc.y = p * v.y; acc.z = p * v.z; acc.w = p * v.w;
    }
    int rs = g_rowstart[d], re = g_rowstart[d + 1];
    for (int i = rs; i < re; i++) {
        int s = g_esrc[i];
        float p = g_p1[i * H1 + h];
        float4 v = ((const float4*)&g_xl1[s * C1])[t];
        acc.x = fmaf(p, v.x, acc.x); acc.y = fmaf(p, v.y, acc.y);
        acc.z = fmaf(p, v.z, acc.z); acc.w = fmaf(p, v.w, acc.w);
    }
    float inv = 1.f / g_den1[d * H1 + h];
    float4 bb = __ldg((const float4*)b1 + t);
    float v0 = acc.x * inv + bb.x; v0 = v0 > 0.f ? v0 : (__expf(v0) - 1.f);
    float v1 = acc.y * inv + bb.y; v1 = v1 > 0.f ? v1 : (__expf(v1) - 1.f);
    float v2 = acc.z * inv + bb.z; v2 = v2 > 0.f ? v2 : (__expf(v2) - 1.f);
    float v3 = acc.w * inv + bb.w; v3 = v3 > 0.f ? v3 : (__expf(v3) - 1.f);
    ((float4*)&g_h1[d * C1])[t] = make_float4(v0, v1, v2, v3);
}

// ---------------- layer-2 attention: warp/edge, fused ----------------
__global__ void k_att2(const int* __restrict__ src, const int* __restrict__ dst,
                       const float* __restrict__ ea, const float* __restrict__ W2e,
                       const float* __restrict__ att2, int E, int N) {
    int gw = (blockIdx.x * blockDim.x + threadIdx.x) >> 5;
    int lane = threadIdx.x & 31;
    if (gw >= E + N) return;
    int s, d, outIdx; float e0, e1;
    if (gw < E) {
        s = __ldg(src + gw); d = __ldg(dst + gw);
        float2 a2 = __ldg((const float2*)ea + gw);
        e0 = a2.x; e1 = a2.y;
        outIdx = g_epos[gw];
    } else {
        s = d = gw - E;
        e0 = g_loopea[2 * d]; e1 = g_loopea[2 * d + 1];
        outIdx = -1;
    }
    float4 l = ((const float4*)&g_xl2[s * C2])[lane];
    float4 r = ((const float4*)&g_xr2[d * C2])[lane];
    float4 w0 = __ldg((const float4*)W2e + lane);
    float4 w1 = __ldg((const float4*)(W2e + C2) + lane);
    float4 a = __ldg((const float4*)att2 + lane);
    float zx = l.x + r.x + e0 * w0.x + e1 * w1.x; zx = zx > 0.f ? zx : 0.2f * zx;
    float zy = l.y + r.y + e0 * w0.y + e1 * w1.y; zy = zy > 0.f ? zy : 0.2f * zy;
    float zz = l.z + r.z + e0 * w0.z + e1 * w1.z; zz = zz > 0.f ? zz : 0.2f * zz;
    float zw = l.w + r.w + e0 * w0.w + e1 * w1.w; zw = zw > 0.f ? zw : 0.2f * zw;
    float acc = a.x * zx + a.y * zy + a.z * zz + a.w * zw;
#pragma unroll
    for (int o = 16; o > 0; o >>= 1) acc += __shfl_xor_sync(0xffffffffu, acc, o);
    if (lane == 0) {
        float p = __expf(acc);
        if (outIdx >= 0) g_p2[outIdx] = p;
        else             g_ps2[d] = p;
        atomicAdd(&g_den2[d], p);
    }
}

// ---------------- layer-2 aggregation + ELU + fused FC; warp per node ----------------
__global__ void k_agg2(const float* __restrict__ b2, const float* __restrict__ Wfc,
                       const float* __restrict__ bfc, float* __restrict__ out, int N) {
    int node = blockIdx.x * 4 + (threadIdx.x >> 5);
    int lane = threadIdx.x & 31;
    if (node >= N) return;
    float4 acc;
    {
        float p = g_ps2[node];
        float4 v = ((const float4*)&g_xl2[node * C2])[lane];
        acc.x = p * v.x; acc.y = p * v.y; acc.z = p * v.z; acc.w = p * v.w;
    }
    int rs = g_rowstart[node], re = g_rowstart[node + 1];
    for (int i = rs; i < re; i++) {
        int s = g_esrc[i];
        float p = g_p2[i];
        float4 v = ((const float4*)&g_xl2[s * C2])[lane];
        acc.x = fmaf(p, v.x, acc.x); acc.y = fmaf(p, v.y, acc.y);
        acc.z = fmaf(p, v.z, acc.z); acc.w = fmaf(p, v.w, acc.w);
    }
    float inv = 1.f / g_den2[node];
    float4 bb = __ldg((const float4*)b2 + lane);
    float v0 = acc.x * inv + bb.x; v0 = v0 > 0.f ? v0 : (__expf(v0) - 1.f);
    float v1 = acc.y * inv + bb.y; v1 = v1 > 0.f ? v1 : (__expf(v1) - 1.f);
    float v2 = acc.z * inv + bb.z; v2 = v2 > 0.f ? v2 : (__expf(v2) - 1.f);
    float v3 = acc.w * inv + bb.w; v3 = v3 > 0.f ? v3 : (__expf(v3) - 1.f);
    // Wfc is [128][2] row-major; channels 4*lane..4*lane+3 -> Wfc[8*lane .. 8*lane+7]
    float4 wA = __ldg((const float4*)Wfc + 2 * lane);
    float4 wB = __ldg((const float4*)Wfc + 2 * lane + 1);
    float o0 = v0 * wA.x + v1 * wA.z + v2 * wB.x + v3 * wB.z;
    float o1 = v0 * wA.y + v1 * wA.w + v2 * wB.y + v3 * wB.w;
#pragma unroll
    for (int o = 16; o > 0; o >>= 1) {
        o0 += __shfl_xor_sync(0xffffffffu, o0, o);
        o1 += __shfl_xor_sync(0xffffffffu, o1, o);
    }
    if (lane == 0) {
        out[2 * node]     = o0 + __ldg(bfc);
        out[2 * node + 1] = o1 + __ldg(bfc + 1);
    }
}

// ---------------- launch ----------------
extern "C" void kernel_launch(void* const* d_in, const int* in_sizes, int n_in,
                              void* d_out, int out_size) {
    const float* x    = (const float*)d_in[0];
    const int*   ei   = (const int*)  d_in[1];
    const float* ea   = (const float*)d_in[2];
    const int*   rt   = (const int*)  d_in[3];
    const float* aaem = (const float*)d_in[4];
    const float* W1l  = (const float*)d_in[5];
    const float* W1r  = (const float*)d_in[6];
    const float* W1e  = (const float*)d_in[7];
    const float* att1 = (const float*)d_in[8];
    const float* b1   = (const float*)d_in[9];
    const float* W2l  = (const float*)d_in[10];
    const float* W2r  = (const float*)d_in[11];
    const float* W2e  = (const float*)d_in[12];
    const float* att2 = (const float*)d_in[13];
    const float* b2   = (const float*)d_in[14];
    const float* Wfc  = (const float*)d_in[15];
    const float* bfc  = (const float*)d_in[16];
    float* out = (float*)d_out;

    int N = in_sizes[0] / 5;
    int E = in_sizes[1] / 2;
    if (N > MAXN) N = MAXN;
    if (E > MAXE) E = MAXE;
    const int* src = ei;
    const int* dst = ei + E;
    int NP_BLK = (N + 63) / 64;

    k_init<<<(N + 255) / 256, 256>>>(N);
    k_h0<<<(N * TOTINP + 255) / 256, 256>>>(x, rt, aaem, N);
    k_deg<<<(E + 255) / 256, 256>>>(dst, ea, E);
    k_scan<<<1, 1024>>>(N);
    k_scatter<<<(E + 255) / 256, 256>>>(src, dst, E);

    k_gemm1<<<dim3(NP_BLK, 4, 2), 256>>>(W1l, W1r, N);
    k_att1<<<(E + N + 7) / 8, 256>>>(src, dst, ea, W1e, att1, E, N);
    k_agg1<<<N, 128>>>(b1, N);

    k_gemm2<<<dim3(NP_BLK, 1, 2), 256>>>(W2l, W2r, N);
    k_att2<<<(E + N + 7) / 8, 256>>>(src, dst, ea, W2e, att2, E, N);
    k_agg2<<<(N + 3) / 4, 128>>>(b2, Wfc, bfc, out, N);
}

// round 4
// speedup vs baseline: 1.5327x; 1.1983x over previous
#include <cuda_runtime.h>
#include <mma.h>
#include <math.h>
#include <float.h>

using namespace nvcuda;

#define MAXN 20000
#define MAXNP 20032
#define MAXE 150000
#define TOTINP 40
#define C1 512
#define H1 4
#define C2 128
#define PCAP 256            // smem p-cache per head/warp (deg rarely > 30)

// ---------------- scratch ----------------
static __device__ float g_h0[MAXNP * TOTINP];
static __device__ float g_xl1[MAXNP * C1];
static __device__ float g_xr1[MAXNP * C1];
static __device__ float g_h1[MAXNP * C1];
static __device__ float g_xl2[MAXNP * C2];
static __device__ float g_xr2[MAXNP * C2];
static __device__ float g_p1[MAXE * H1];     // overflow fallback only
static __device__ float g_p2[MAXE];          // overflow fallback only
static __device__ float g_easum[MAXN * 2];
static __device__ float g_loopea[MAXN * 2];
static __device__ int   g_deg[MAXN];
static __device__ int   g_rowstart[MAXN + 1];
static __device__ int   g_cursor[MAXN];
static __device__ int   g_esrc[MAXE];        // src permuted into CSR order
static __device__ float2 g_eea[MAXE];        // edge_attr permuted into CSR order
static __device__ int   g_blocksum[32];
static __device__ int   g_blockoff[32];
static __device__ int   g_total;

// ---------------- init ----------------
__global__ void k_init(int N) {
    int i = blockIdx.x * blockDim.x + threadIdx.x;
    if (i >= N) return;
    g_deg[i] = 0;
    g_cursor[i] = 0;
    g_easum[2 * i] = 0.f;
    g_easum[2 * i + 1] = 0.f;
}

// ---------------- h0 = concat(x, aa_emb[residue_type]), padded to 40 ----------------
__global__ void k_h0(const float* __restrict__ x, const int* __restrict__ rt,
                     const float* __restrict__ aaemb, int N) {
    int i = blockIdx.x * blockDim.x + threadIdx.x;
    if (i >= N * TOTINP) return;
    int n = i / TOTINP, c = i - n * TOTINP;
    float v = 0.f;
    if (c < 5) v = x[n * 5 + c];
    else if (c < 37) v = aaemb[rt[n] * 32 + (c - 5)];
    g_h0[i] = v;
}

// ---------------- degree + edge-attr sums ----------------
__global__ void k_deg(const int* __restrict__ dst, const float* __restrict__ ea, int E) {
    int e = blockIdx.x * blockDim.x + threadIdx.x;
    if (e >= E) return;
    int d = dst[e];
    float2 a = ((const float2*)ea)[e];
    atomicAdd(&g_deg[d], 1);
    atomicAdd(&g_easum[2 * d], a.x);
    atomicAdd(&g_easum[2 * d + 1], a.y);
}

// ---------------- parallel 3-phase scan ----------------
__global__ void k_scan1(int N) {
    __shared__ int sm[1024];
    int i = blockIdx.x * 1024 + threadIdx.x;
    int v = (i < N) ? g_deg[i] : 0;
    sm[threadIdx.x] = v;
    __syncthreads();
    for (int o = 1; o < 1024; o <<= 1) {
        int t = (threadIdx.x >= o) ? sm[threadIdx.x - o] : 0;
        __syncthreads();
        sm[threadIdx.x] += t;
        __syncthreads();
    }
    if (i < N) g_rowstart[i] = sm[threadIdx.x] - v;   // block-local exclusive
    if (threadIdx.x == 1023) g_blocksum[blockIdx.x] = sm[1023];
}
__global__ void k_scan2(int nb) {
    if (threadIdx.x == 0) {
        int run = 0;
        for (int b = 0; b < nb; b++) { g_blockoff[b] = run; run += g_blocksum[b]; }
        g_total = run;
    }
}
__global__ void k_scan3(int N) {
    int i = blockIdx.x * blockDim.x + threadIdx.x;
    if (i < N) {
        g_rowstart[i] += g_blockoff[i >> 10];
        int dg = g_deg[i];
        float fd = (dg < 1) ? 1.f : (float)dg;
        g_loopea[2 * i]     = g_easum[2 * i] / fd;
        g_loopea[2 * i + 1] = g_easum[2 * i + 1] / fd;
    }
    if (i == 0) g_rowstart[N] = g_total;
}

__global__ void k_scatter(const int* __restrict__ src, const int* __restrict__ dst,
                          const float* __restrict__ ea, int E) {
    int e = blockIdx.x * blockDim.x + threadIdx.x;
    if (e >= E) return;
    int d = dst[e];
    int pos = g_rowstart[d] + atomicAdd(&g_cursor[d], 1);
    g_esrc[pos] = src[e];
    g_eea[pos] = ((const float2*)ea)[e];
}

// ---------------- layer-1 GEMM (tf32 WMMA): [NP,40] @ [40,512] ----------------
__global__ void __launch_bounds__(256) k_gemm1(const float* __restrict__ Wl,
                                               const float* __restrict__ Wr, int N) {
    const float* W = blockIdx.z ? Wr : Wl;
    float* out = blockIdx.z ? g_xr1 : g_xl1;
    __shared__ float As[64 * 44];
    __shared__ float Bs[40 * 132];
    int tid = threadIdx.x;
    int n0 = blockIdx.x * 64;
    int col0 = blockIdx.y * 128;
    for (int idx = tid; idx < 64 * 40; idx += 256) {
        int r = idx / 40, c = idx - r * 40;
        float v = (n0 + r < N) ? g_h0[(n0 + r) * TOTINP + c] : 0.f;
        As[r * 44 + c] = wmma::__float_to_tf32(v);
    }
    for (int idx = tid; idx < 40 * 128; idx += 256) {
        int r = idx >> 7, c = idx & 127;
        float v = (r < 37) ? W[r * C1 + col0 + c] : 0.f;
        Bs[r * 132 + c] = wmma::__float_to_tf32(v);
    }
    __syncthreads();
    int wid = tid >> 5;
    int wr = wid & 1, wc = wid >> 1;
    wmma::fragment<wmma::accumulator, 16, 16, 8, float> acc[2][2];
#pragma unroll
    for (int i = 0; i < 2; i++)
#pragma unroll
        for (int j = 0; j < 2; j++) wmma::fill_fragment(acc[i][j], 0.f);
#pragma unroll
    for (int k0 = 0; k0 < 40; k0 += 8) {
        wmma::fragment<wmma::matrix_a, 16, 16, 8, wmma::precision::tf32, wmma::row_major> a[2];
        wmma::fragment<wmma::matrix_b, 16, 16, 8, wmma::precision::tf32, wmma::row_major> b[2];
#pragma unroll
        for (int i = 0; i < 2; i++)
            wmma::load_matrix_sync(a[i], &As[(wr * 32 + i * 16) * 44 + k0], 44);
#pragma unroll
        for (int j = 0; j < 2; j++)
            wmma::load_matrix_sync(b[j], &Bs[k0 * 132 + wc * 32 + j * 16], 132);
#pragma unroll
        for (int i = 0; i < 2; i++)
#pragma unroll
            for (int j = 0; j < 2; j++)
                wmma::mma_sync(acc[i][j], a[i], b[j], acc[i][j]);
    }
#pragma unroll
    for (int i = 0; i < 2; i++)
#pragma unroll
        for (int j = 0; j < 2; j++)
            wmma::store_matrix_sync(&out[(n0 + wr * 32 + i * 16) * C1 + col0 + wc * 32 + j * 16],
                                    acc[i][j], C1, wmma::mem_row_major);
}

// ---------------- layer-2 GEMM (tf32 WMMA): [NP,512] @ [512,128] ----------------
__global__ void __launch_bounds__(256) k_gemm2(const float* __restrict__ Wl,
                                               const float* __restrict__ Wr, int N) {
    const float* W = blockIdx.z ? Wr : Wl;
    float* out = blockIdx.z ? g_xr2 : g_xl2;
    __shared__ float As[64 * 36];
    __shared__ float Bs[32 * 132];
    int tid = threadIdx.x;
    int n0 = blockIdx.x * 64;
    int wid = tid >> 5;
    int wr = wid & 1, wc = wid >> 1;
    wmma::fragment<wmma::accumulator, 16, 16, 8, float> acc[2][2];
#pragma unroll
    for (int i = 0; i < 2; i++)
#pragma unroll
        for (int j = 0; j < 2; j++) wmma::fill_fragment(acc[i][j], 0.f);
    for (int k0 = 0; k0 < C1; k0 += 32) {
        for (int idx = tid; idx < 64 * 32; idx += 256) {
            int r = idx >> 5, c = idx & 31;
            float v = (n0 + r < N) ? g_h1[(n0 + r) * C1 + k0 + c] : 0.f;
            As[r * 36 + c] = wmma::__float_to_tf32(v);
        }
        for (int idx = tid; idx < 32 * 128; idx += 256) {
            int r = idx >> 7, c = idx & 127;
            Bs[r * 132 + c] = wmma::__float_to_tf32(W[(k0 + r) * C2 + c]);
        }
        __syncthreads();
#pragma unroll
        for (int kk = 0; kk < 32; kk += 8) {
            wmma::fragment<wmma::matrix_a, 16, 16, 8, wmma::precision::tf32, wmma::row_major> a[2];
            wmma::fragment<wmma::matrix_b, 16, 16, 8, wmma::precision::tf32, wmma::row_major> b[2];
#pragma unroll
            for (int i = 0; i < 2; i++)
                wmma::load_matrix_sync(a[i], &As[(wr * 32 + i * 16) * 36 + kk], 36);
#pragma unroll
            for (int j = 0; j < 2; j++)
                wmma::load_matrix_sync(b[j], &Bs[kk * 132 + wc * 32 + j * 16], 132);
#pragma unroll
            for (int i = 0; i < 2; i++)
#pragma unroll
                for (int j = 0; j < 2; j++)
                    wmma::mma_sync(acc[i][j], a[i], b[j], acc[i][j]);
        }
        __syncthreads();
    }
#pragma unroll
    for (int i = 0; i < 2; i++)
#pragma unroll
        for (int j = 0; j < 2; j++)
            wmma::store_matrix_sync(&out[(n0 + wr * 32 + i * 16) * C2 + wc * 32 + j * 16],
                                    acc[i][j], C2, wmma::mem_row_major);
}

// helper: leakyrelu dot term for a float4 group
__device__ __forceinline__ float lrelu_dot(float4 L, float4 R, float e0, float e1,
                                           float4 W0, float4 W1_, float4 A) {
    float zx = L.x + R.x + e0 * W0.x + e1 * W1_.x; zx = zx > 0.f ? zx : 0.2f * zx;
    float zy = L.y + R.y + e0 * W0.y + e1 * W1_.y; zy = zy > 0.f ? zy : 0.2f * zy;
    float zz = L.z + R.z + e0 * W0.z + e1 * W1_.z; zz = zz > 0.f ? zz : 0.2f * zz;
    float zw = L.w + R.w + e0 * W0.w + e1 * W1_.w; zw = zw > 0.f ? zw : 0.2f * zw;
    return A.x * zx + A.y * zy + A.z * zz + A.w * zw;
}

// ---------------- layer-1 fused attention + aggregation: block(128) per node ----------------
// warp h owns head h (channels h*128 .. h*128+127, float4 per lane).
__global__ void __launch_bounds__(128) k_edge1(const float* __restrict__ W1e,
                                               const float* __restrict__ att,
                                               const float* __restrict__ b1, int N) {
    __shared__ float ps[H1][PCAP];
    int d = blockIdx.x;
    int lane = threadIdx.x & 31, h = threadIdx.x >> 5;
    int seg = (h * 128 >> 2) + lane;                 // float4 index of this lane's group
    float4 R  = ((const float4*)&g_xr1[d * C1])[seg - (h * 32) + h * 32]; // = [seg] within row
    R = ((const float4*)(g_xr1 + d * C1))[h * 32 + lane];
    float4 W0 = __ldg((const float4*)W1e + h * 32 + lane);
    float4 W1_ = __ldg((const float4*)(W1e + C1) + h * 32 + lane);
    float4 A  = __ldg((const float4*)att + h * 32 + lane);
    int rs = g_rowstart[d], re = g_rowstart[d + 1];
    float den = 0.f, p_self;
    {
        float e0 = g_loopea[2 * d], e1 = g_loopea[2 * d + 1];
        float4 L = ((const float4*)(g_xl1 + d * C1))[h * 32 + lane];
        float part = lrelu_dot(L, R, e0, e1, W0, W1_, A);
#pragma unroll
        for (int o = 16; o > 0; o >>= 1) part += __shfl_xor_sync(0xffffffffu, part, o);
        p_self = __expf(part);
        den += p_self;
    }
    for (int i = rs; i < re; i++) {
        int s = g_esrc[i];
        float2 e = g_eea[i];
        float4 L = ((const float4*)(g_xl1 + (long)s * C1))[h * 32 + lane];
        float part = lrelu_dot(L, R, e.x, e.y, W0, W1_, A);
#pragma unroll
        for (int o = 16; o > 0; o >>= 1) part += __shfl_xor_sync(0xffffffffu, part, o);
        float p = __expf(part);
        den += p;
        int k = i - rs;
        if (k < PCAP) { if (lane == 0) ps[h][k] = p; }
        else          { if (lane == 0) g_p1[i * H1 + h] = p; }
    }
    __syncwarp();
    float inv = 1.f / den;
    float4 acc;
    {
        float4 L = ((const float4*)(g_xl1 + d * C1))[h * 32 + lane];
        acc.x = p_self * L.x; acc.y = p_self * L.y; acc.z = p_self * L.z; acc.w = p_self * L.w;
    }
    for (int i = rs; i < re; i++) {
        int s = g_esrc[i];
        int k = i - rs;
        float p = (k < PCAP) ? ps[h][k] : __ldg(&g_p1[i * H1 + h]);
        float4 L = ((const float4*)(g_xl1 + (long)s * C1))[h * 32 + lane];
        acc.x = fmaf(p, L.x, acc.x); acc.y = fmaf(p, L.y, acc.y);
        acc.z = fmaf(p, L.z, acc.z); acc.w = fmaf(p, L.w, acc.w);
    }
    float4 bb = __ldg((const float4*)b1 + h * 32 + lane);
    float v0 = acc.x * inv + bb.x; v0 = v0 > 0.f ? v0 : (__expf(v0) - 1.f);
    float v1 = acc.y * inv + bb.y; v1 = v1 > 0.f ? v1 : (__expf(v1) - 1.f);
    float v2 = acc.z * inv + bb.z; v2 = v2 > 0.f ? v2 : (__expf(v2) - 1.f);
    float v3 = acc.w * inv + bb.w; v3 = v3 > 0.f ? v3 : (__expf(v3) - 1.f);
    ((float4*)(g_h1 + d * C1))[h * 32 + lane] = make_float4(v0, v1, v2, v3);
}

// ---------------- layer-2 fused att + agg + ELU + FC: warp per node ----------------
__global__ void __launch_bounds__(256) k_edge2(const float* __restrict__ W2e,
                                               const float* __restrict__ att2,
                                               const float* __restrict__ b2,
                                               const float* __restrict__ Wfc,
                                               const float* __restrict__ bfc,
                                               float* __restrict__ out, int N) {
    __shared__ float ps[8][PCAP];
    int w = threadIdx.x >> 5, lane = threadIdx.x & 31;
    int node = blockIdx.x * 8 + w;
    if (node >= N) return;
    float4 R  = ((const float4*)(g_xr2 + node * C2))[lane];
    float4 W0 = __ldg((const float4*)W2e + lane);
    float4 W1_ = __ldg((const float4*)(W2e + C2) + lane);
    float4 A  = __ldg((const float4*)att2 + lane);
    int rs = g_rowstart[node], re = g_rowstart[node + 1];
    float den = 0.f, p_self;
    {
        float e0 = g_loopea[2 * node], e1 = g_loopea[2 * node + 1];
        float4 L = ((const float4*)(g_xl2 + node * C2))[lane];
        float part = lrelu_dot(L, R, e0, e1, W0, W1_, A);
#pragma unroll
        for (int o = 16; o > 0; o >>= 1) part += __shfl_xor_sync(0xffffffffu, part, o);
        p_self = __expf(part);
        den += p_self;
    }
    for (int i = rs; i < re; i++) {
        int s = g_esrc[i];
        float2 e = g_eea[i];
        float4 L = ((const float4*)(g_xl2 + (long)s * C2))[lane];
        float part = lrelu_dot(L, R, e.x, e.y, W0, W1_, A);
#pragma unroll
        for (int o = 16; o > 0; o >>= 1) part += __shfl_xor_sync(0xffffffffu, part, o);
        float p = __expf(part);
        den += p;
        int k = i - rs;
        if (k < PCAP) { if (lane == 0) ps[w][k] = p; }
        else          { if (lane == 0) g_p2[i] = p; }
    }
    __syncwarp();
    float inv = 1.f / den;
    float4 acc;
    {
        float4 L = ((const float4*)(g_xl2 + node * C2))[lane];
        acc.x = p_self * L.x; acc.y = p_self * L.y; acc.z = p_self * L.z; acc.w = p_self * L.w;
    }
    for (int i = rs; i < re; i++) {
        int s = g_esrc[i];
        int k = i - rs;
        float p = (k < PCAP) ? ps[w][k] : __ldg(&g_p2[i]);
        float4 L = ((const float4*)(g_xl2 + (long)s * C2))[lane];
        acc.x = fmaf(p, L.x, acc.x); acc.y = fmaf(p, L.y, acc.y);
        acc.z = fmaf(p, L.z, acc.z); acc.w = fmaf(p, L.w, acc.w);
    }
    float4 bb = __ldg((const float4*)b2 + lane);
    float v0 = acc.x * inv + bb.x; v0 = v0 > 0.f ? v0 : (__expf(v0) - 1.f);
    float v1 = acc.y * inv + bb.y; v1 = v1 > 0.f ? v1 : (__expf(v1) - 1.f);
    float v2 = acc.z * inv + bb.z; v2 = v2 > 0.f ? v2 : (__expf(v2) - 1.f);
    float v3 = acc.w * inv + bb.w; v3 = v3 > 0.f ? v3 : (__expf(v3) - 1.f);
    float4 wA = __ldg((const float4*)Wfc + 2 * lane);
    float4 wB = __ldg((const float4*)Wfc + 2 * lane + 1);
    float o0 = v0 * wA.x + v1 * wA.z + v2 * wB.x + v3 * wB.z;
    float o1 = v0 * wA.y + v1 * wA.w + v2 * wB.y + v3 * wB.w;
#pragma unroll
    for (int o = 16; o > 0; o >>= 1) {
        o0 += __shfl_xor_sync(0xffffffffu, o0, o);
        o1 += __shfl_xor_sync(0xffffffffu, o1, o);
    }
    if (lane == 0) {
        out[2 * node]     = o0 + __ldg(bfc);
        out[2 * node + 1] = o1 + __ldg(bfc + 1);
    }
}

// ---------------- launch ----------------
extern "C" void kernel_launch(void* const* d_in, const int* in_sizes, int n_in,
                              void* d_out, int out_size) {
    const float* x    = (const float*)d_in[0];
    const int*   ei   = (const int*)  d_in[1];
    const float* ea   = (const float*)d_in[2];
    const int*   rt   = (const int*)  d_in[3];
    const float* aaem = (const float*)d_in[4];
    const float* W1l  = (const float*)d_in[5];
    const float* W1r  = (const float*)d_in[6];
    const float* W1e  = (const float*)d_in[7];
    const float* att1 = (const float*)d_in[8];
    const float* b1   = (const float*)d_in[9];
    const float* W2l  = (const float*)d_in[10];
    const float* W2r  = (const float*)d_in[11];
    const float* W2e  = (const float*)d_in[12];
    const float* att2 = (const float*)d_in[13];
    const float* b2   = (const float*)d_in[14];
    const float* Wfc  = (const float*)d_in[15];
    const float* bfc  = (const float*)d_in[16];
    float* out = (float*)d_out;

    int N = in_sizes[0] / 5;
    int E = in_sizes[1] / 2;
    if (N > MAXN) N = MAXN;
    if (E > MAXE) E = MAXE;
    const int* src = ei;
    const int* dst = ei + E;
    int NP_BLK = (N + 63) / 64;
    int nb = (N + 1023) / 1024;

    k_init<<<(N + 255) / 256, 256>>>(N);
    k_h0<<<(N * TOTINP + 255) / 256, 256>>>(x, rt, aaem, N);
    k_deg<<<(E + 255) / 256, 256>>>(dst, ea, E);
    k_scan1<<<nb, 1024>>>(N);
    k_scan2<<<1, 32>>>(nb);
    k_scan3<<<(N + 255) / 256, 256>>>(N);
    k_scatter<<<(E + 255) / 256, 256>>>(src, dst, ea, E);

    k_gemm1<<<dim3(NP_BLK, 4, 2), 256>>>(W1l, W1r, N);
    k_edge1<<<N, 128>>>(W1e, att1, b1, N);

    k_gemm2<<<dim3(NP_BLK, 1, 2), 256>>>(W2l, W2r, N);
    k_edge2<<<(N + 7) / 8, 256>>>(W2e, att2, b2, Wfc, bfc, out, N);
}

// round 6
// speedup vs baseline: 1.6823x; 1.0976x over previous
#include <cuda_runtime.h>
#include <mma.h>
#include <math.h>
#include <float.h>

using namespace nvcuda;

#define MAXN 20000
#define MAXNP 20032
#define MAXE 150000
#define TOTINP 40
#define C1 512
#define H1 4
#define C2 128

// ---------------- scratch ----------------
static __device__ float g_h0[MAXNP * TOTINP];
static __device__ float g_xl1[MAXNP * C1];
static __device__ float g_xr1[MAXNP * C1];
static __device__ float g_h1[MAXNP * C1];
static __device__ float g_xl2[MAXNP * C2];
static __device__ float g_xr2[MAXNP * C2];
static __device__ float g_easum[MAXN * 2];
static __device__ float g_loopea[MAXN * 2];
static __device__ int   g_deg[MAXN];
static __device__ int   g_rowstart[MAXN + 1];
static __device__ int   g_cursor[MAXN];
static __device__ int   g_esrc[MAXE];        // src permuted into CSR order
static __device__ float2 g_eea[MAXE];        // edge_attr permuted into CSR order
static __device__ int   g_blocksum[32];      // only [0,nb) ever written

// ---------------- init + h0 = concat(x, aa_emb[residue_type]) ----------------
__global__ void k_h0(const float* __restrict__ x, const int* __restrict__ rt,
                     const float* __restrict__ aaemb, int N) {
    int i = blockIdx.x * blockDim.x + threadIdx.x;
    if (i < N) {                      // per-node init folded in
        g_deg[i] = 0;
        g_cursor[i] = 0;
        g_easum[2 * i] = 0.f;
        g_easum[2 * i + 1] = 0.f;
    }
    if (i >= N * TOTINP) return;
    int n = i / TOTINP, c = i - n * TOTINP;
    float v = 0.f;
    if (c < 5) v = x[n * 5 + c];
    else if (c < 37) v = aaemb[rt[n] * 32 + (c - 5)];
    g_h0[i] = v;
}

// ---------------- degree + edge-attr sums ----------------
__global__ void k_deg(const int* __restrict__ dst, const float* __restrict__ ea, int E) {
    int e = blockIdx.x * blockDim.x + threadIdx.x;
    if (e >= E) return;
    int d = dst[e];
    float2 a = ((const float2*)ea)[e];
    atomicAdd(&g_deg[d], 1);
    atomicAdd(&g_easum[2 * d], a.x);
    atomicAdd(&g_easum[2 * d + 1], a.y);
}

// ---------------- parallel scan (2 kernels) ----------------
__global__ void k_scan1(int N) {
    __shared__ int sm[1024];
    int i = blockIdx.x * 1024 + threadIdx.x;
    int v = (i < N) ? g_deg[i] : 0;
    sm[threadIdx.x] = v;
    __syncthreads();
    for (int o = 1; o < 1024; o <<= 1) {
        int t = (threadIdx.x >= o) ? sm[threadIdx.x - o] : 0;
        __syncthreads();
        sm[threadIdx.x] += t;
        __syncthreads();
    }
    if (i < N) g_rowstart[i] = sm[threadIdx.x] - v;   // block-local exclusive
    if (threadIdx.x == 1023) g_blocksum[blockIdx.x] = sm[1023];
}
// adds block offsets (warp-scan of <=32 block sums) + computes loop edge-attr mean
__global__ void k_scan3(int N, int nb) {
    __shared__ int soff[32];
    int t = threadIdx.x;
    if (t < 32) {
        int v = (t < nb) ? g_blocksum[t] : 0;
        int s = v;
#pragma unroll
        for (int o = 1; o < 32; o <<= 1) {
            int u = __shfl_up_sync(0xffffffffu, s, o);
            if (t >= o) s += u;
        }
        soff[t] = s - v;   // exclusive; soff[31] == total (sums >= nb are 0)
    }
    __syncthreads();
    int i = blockIdx.x * blockDim.x + t;
    if (i < N) {
        g_rowstart[i] += soff[i >> 10];
        int dg = g_deg[i];
        float fd = (dg < 1) ? 1.f : (float)dg;
        g_loopea[2 * i]     = g_easum[2 * i] / fd;
        g_loopea[2 * i + 1] = g_easum[2 * i + 1] / fd;
    }
    if (i == 0) g_rowstart[N] = soff[31];
}

__global__ void k_scatter(const int* __restrict__ src, const int* __restrict__ dst,
                          const float* __restrict__ ea, int E) {
    int e = blockIdx.x * blockDim.x + threadIdx.x;
    if (e >= E) return;
    int d = dst[e];
    int pos = g_rowstart[d] + atomicAdd(&g_cursor[d], 1);
    g_esrc[pos] = src[e];
    g_eea[pos] = ((const float2*)ea)[e];
}

// ---------------- layer-1 GEMM (tf32 WMMA): [NP,40] @ [40,512] ----------------
__global__ void __launch_bounds__(256) k_gemm1(const float* __restrict__ Wl,
                                               const float* __restrict__ Wr, int N) {
    const float* W = blockIdx.z ? Wr : Wl;
    float* out = blockIdx.z ? g_xr1 : g_xl1;
    __shared__ float As[64 * 44];
    __shared__ float Bs[40 * 132];
    int tid = threadIdx.x;
    int n0 = blockIdx.x * 64;
    int col0 = blockIdx.y * 128;
    for (int idx = tid; idx < 64 * 40; idx += 256) {
        int r = idx / 40, c = idx - r * 40;
        float v = (n0 + r < N) ? g_h0[(n0 + r) * TOTINP + c] : 0.f;
        As[r * 44 + c] = wmma::__float_to_tf32(v);
    }
    for (int idx = tid; idx < 40 * 128; idx += 256) {
        int r = idx >> 7, c = idx & 127;
        float v = (r < 37) ? W[r * C1 + col0 + c] : 0.f;
        Bs[r * 132 + c] = wmma::__float_to_tf32(v);
    }
    __syncthreads();
    int wid = tid >> 5;
    int wr = wid & 1, wc = wid >> 1;
    wmma::fragment<wmma::accumulator, 16, 16, 8, float> acc[2][2];
#pragma unroll
    for (int i = 0; i < 2; i++)
#pragma unroll
        for (int j = 0; j < 2; j++) wmma::fill_fragment(acc[i][j], 0.f);
#pragma unroll
    for (int k0 = 0; k0 < 40; k0 += 8) {
        wmma::fragment<wmma::matrix_a, 16, 16, 8, wmma::precision::tf32, wmma::row_major> a[2];
        wmma::fragment<wmma::matrix_b, 16, 16, 8, wmma::precision::tf32, wmma::row_major> b[2];
#pragma unroll
        for (int i = 0; i < 2; i++)
            wmma::load_matrix_sync(a[i], &As[(wr * 32 + i * 16) * 44 + k0], 44);
#pragma unroll
        for (int j = 0; j < 2; j++)
            wmma::load_matrix_sync(b[j], &Bs[k0 * 132 + wc * 32 + j * 16], 132);
#pragma unroll
        for (int i = 0; i < 2; i++)
#pragma unroll
            for (int j = 0; j < 2; j++)
                wmma::mma_sync(acc[i][j], a[i], b[j], acc[i][j]);
    }
#pragma unroll
    for (int i = 0; i < 2; i++)
#pragma unroll
        for (int j = 0; j < 2; j++)
            wmma::store_matrix_sync(&out[(n0 + wr * 32 + i * 16) * C1 + col0 + wc * 32 + j * 16],
                                    acc[i][j], C1, wmma::mem_row_major);
}

// ---------------- layer-2 GEMM (tf32 WMMA): [NP,512] @ [512,128] ----------------
__global__ void __launch_bounds__(256) k_gemm2(const float* __restrict__ Wl,
                                               const float* __restrict__ Wr, int N) {
    const float* W = blockIdx.z ? Wr : Wl;
    float* out = blockIdx.z ? g_xr2 : g_xl2;
    __shared__ float As[64 * 36];
    __shared__ float Bs[32 * 132];
    int tid = threadIdx.x;
    int n0 = blockIdx.x * 64;
    int wid = tid >> 5;
    int wr = wid & 1, wc = wid >> 1;
    wmma::fragment<wmma::accumulator, 16, 16, 8, float> acc[2][2];
#pragma unroll
    for (int i = 0; i < 2; i++)
#pragma unroll
        for (int j = 0; j < 2; j++) wmma::fill_fragment(acc[i][j], 0.f);
    for (int k0 = 0; k0 < C1; k0 += 32) {
        for (int idx = tid; idx < 64 * 32; idx += 256) {
            int r = idx >> 5, c = idx & 31;
            float v = (n0 + r < N) ? g_h1[(n0 + r) * C1 + k0 + c] : 0.f;
            As[r * 36 + c] = wmma::__float_to_tf32(v);
        }
        for (int idx = tid; idx < 32 * 128; idx += 256) {
            int r = idx >> 7, c = idx & 127;
            Bs[r * 132 + c] = wmma::__float_to_tf32(W[(k0 + r) * C2 + c]);
        }
        __syncthreads();
#pragma unroll
        for (int kk = 0; kk < 32; kk += 8) {
            wmma::fragment<wmma::matrix_a, 16, 16, 8, wmma::precision::tf32, wmma::row_major> a[2];
            wmma::fragment<wmma::matrix_b, 16, 16, 8, wmma::precision::tf32, wmma::row_major> b[2];
#pragma unroll
            for (int i = 0; i < 2; i++)
                wmma::load_matrix_sync(a[i], &As[(wr * 32 + i * 16) * 36 + kk], 36);
#pragma unroll
            for (int j = 0; j < 2; j++)
                wmma::load_matrix_sync(b[j], &Bs[kk * 132 + wc * 32 + j * 16], 132);
#pragma unroll
            for (int i = 0; i < 2; i++)
#pragma unroll
                for (int j = 0; j < 2; j++)
                    wmma::mma_sync(acc[i][j], a[i], b[j], acc[i][j]);
        }
        __syncthreads();
    }
#pragma unroll
    for (int i = 0; i < 2; i++)
#pragma unroll
        for (int j = 0; j < 2; j++)
            wmma::store_matrix_sync(&out[(n0 + wr * 32 + i * 16) * C2 + wc * 32 + j * 16],
                                    acc[i][j], C2, wmma::mem_row_major);
}

// helper: leakyrelu dot term for a float4 group
__device__ __forceinline__ float lrelu_dot(float4 L, float4 R, float e0, float e1,
                                           float4 W0, float4 W1_, float4 A) {
    float zx = L.x + R.x + e0 * W0.x + e1 * W1_.x; zx = zx > 0.f ? zx : 0.2f * zx;
    float zy = L.y + R.y + e0 * W0.y + e1 * W1_.y; zy = zy > 0.f ? zy : 0.2f * zy;
    float zz = L.z + R.z + e0 * W0.z + e1 * W1_.z; zz = zz > 0.f ? zz : 0.2f * zz;
    float zw = L.w + R.w + e0 * W0.w + e1 * W1_.w; zw = zw > 0.f ? zw : 0.2f * zw;
    return A.x * zx + A.y * zy + A.z * zz + A.w * zw;
}

// ---------------- layer-1 SINGLE-PASS fused attention+aggregation ----------------
// block(128) per node; warp h owns head h (float4 per lane). After the butterfly
// reduce every lane holds the full logit, so p*L accumulates with L in registers.
__global__ void __launch_bounds__(128) k_edge1(const float* __restrict__ W1e,
                                               const float* __restrict__ att,
                                               const float* __restrict__ b1, int N) {
    int d = blockIdx.x;
    int lane = threadIdx.x & 31, h = threadIdx.x >> 5;
    int c4 = h * 32 + lane;                 // float4 index within a C1 row
    float4 R  = ((const float4*)(g_xr1 + d * C1))[c4];
    float4 W0 = __ldg((const float4*)W1e + c4);
    float4 W1_ = __ldg((const float4*)(W1e + C1) + c4);
    float4 A  = __ldg((const float4*)att + c4);
    int rs = g_rowstart[d], re = g_rowstart[d + 1];
    float den;
    float4 acc;
    {   // self loop
        float e0 = g_loopea[2 * d], e1 = g_loopea[2 * d + 1];
        float4 L = ((const float4*)(g_xl1 + d * C1))[c4];
        float part = lrelu_dot(L, R, e0, e1, W0, W1_, A);
#pragma unroll
        for (int o = 16; o > 0; o >>= 1) part += __shfl_xor_sync(0xffffffffu, part, o);
        float p = __expf(part);
        den = p;
        acc.x = p * L.x; acc.y = p * L.y; acc.z = p * L.z; acc.w = p * L.w;
    }
    int i = rs;
    for (; i + 2 <= re; i += 2) {
        int s0 = g_esrc[i], s1 = g_esrc[i + 1];
        float2 ea0 = g_eea[i], ea1 = g_eea[i + 1];
        float4 L0 = ((const float4*)(g_xl1 + (long)s0 * C1))[c4];
        float4 L1 = ((const float4*)(g_xl1 + (long)s1 * C1))[c4];
        float part0 = lrelu_dot(L0, R, ea0.x, ea0.y, W0, W1_, A);
        float part1 = lrelu_dot(L1, R, ea1.x, ea1.y, W0, W1_, A);
#pragma unroll
        for (int o = 16; o > 0; o >>= 1) {
            part0 += __shfl_xor_sync(0xffffffffu, part0, o);
            part1 += __shfl_xor_sync(0xffffffffu, part1, o);
        }
        float p0 = __expf(part0), p1 = __expf(part1);
        den += p0 + p1;
        acc.x = fmaf(p0, L0.x, fmaf(p1, L1.x, acc.x));
        acc.y = fmaf(p0, L0.y, fmaf(p1, L1.y, acc.y));
        acc.z = fmaf(p0, L0.z, fmaf(p1, L1.z, acc.z));
        acc.w = fmaf(p0, L0.w, fmaf(p1, L1.w, acc.w));
    }
    if (i < re) {
        int s0 = g_esrc[i];
        float2 ea0 = g_eea[i];
        float4 L0 = ((const float4*)(g_xl1 + (long)s0 * C1))[c4];
        float part0 = lrelu_dot(L0, R, ea0.x, ea0.y, W0, W1_, A);
#pragma unroll
        for (int o = 16; o > 0; o >>= 1) part0 += __shfl_xor_sync(0xffffffffu, part0, o);
        float p0 = __expf(part0);
        den += p0;
        acc.x = fmaf(p0, L0.x, acc.x); acc.y = fmaf(p0, L0.y, acc.y);
        acc.z = fmaf(p0, L0.z, acc.z); acc.w = fmaf(p0, L0.w, acc.w);
    }
    float inv = 1.f / den;
    float4 bb = __ldg((const float4*)b1 + c4);
    float v0 = acc.x * inv + bb.x; v0 = v0 > 0.f ? v0 : (__expf(v0) - 1.f);
    float v1 = acc.y * inv + bb.y; v1 = v1 > 0.f ? v1 : (__expf(v1) - 1.f);
    float v2 = acc.z * inv + bb.z; v2 = v2 > 0.f ? v2 : (__expf(v2) - 1.f);
    float v3 = acc.w * inv + bb.w; v3 = v3 > 0.f ? v3 : (__expf(v3) - 1.f);
    ((float4*)(g_h1 + d * C1))[c4] = make_float4(v0, v1, v2, v3);
}

// ---------------- layer-2 SINGLE-PASS fused att+agg+ELU+FC: warp per node ----------------
__global__ void __launch_bounds__(256) k_edge2(const float* __restrict__ W2e,
                                               const float* __restrict__ att2,
                                               const float* __restrict__ b2,
                                               const float* __restrict__ Wfc,
                                               const float* __restrict__ bfc,
                                               float* __restrict__ out, int N) {
    int w = threadIdx.x >> 5, lane = threadIdx.x & 31;
    int node = blockIdx.x * 8 + w;
    if (node >= N) return;
    float4 R  = ((const float4*)(g_xr2 + node * C2))[lane];
    float4 W0 = __ldg((const float4*)W2e + lane);
    float4 W1_ = __ldg((const float4*)(W2e + C2) + lane);
    float4 A  = __ldg((const float4*)att2 + lane);
    int rs = g_rowstart[node], re = g_rowstart[node + 1];
    float den;
    float4 acc;
    {
        float e0 = g_loopea[2 * node], e1 = g_loopea[2 * node + 1];
        float4 L = ((const float4*)(g_xl2 + node * C2))[lane];
        float part = lrelu_dot(L, R, e0, e1, W0, W1_, A);
#pragma unroll
        for (int o = 16; o > 0; o >>= 1) part += __shfl_xor_sync(0xffffffffu, part, o);
        float p = __expf(part);
        den = p;
        acc.x = p * L.x; acc.y = p * L.y; acc.z = p * L.z; acc.w = p * L.w;
    }
    int i = rs;
    for (; i + 2 <= re; i += 2) {
        int s0 = g_esrc[i], s1 = g_esrc[i + 1];
        float2 ea0 = g_eea[i], ea1 = g_eea[i + 1];
        float4 L0 = ((const float4*)(g_xl2 + (long)s0 * C2))[lane];
        float4 L1 = ((const float4*)(g_xl2 + (long)s1 * C2))[lane];
        float part0 = lrelu_dot(L0, R, ea0.x, ea0.y, W0, W1_, A);
        float part1 = lrelu_dot(L1, R, ea1.x, ea1.y, W0, W1_, A);
#pragma unroll
        for (int o = 16; o > 0; o >>= 1) {
            part0 += __shfl_xor_sync(0xffffffffu, part0, o);
            part1 += __shfl_xor_sync(0xffffffffu, part1, o);
        }
        float p0 = __expf(part0), p1 = __expf(part1);
        den += p0 + p1;
        acc.x = fmaf(p0, L0.x, fmaf(p1, L1.x, acc.x));
        acc.y = fmaf(p0, L0.y, fmaf(p1, L1.y, acc.y));
        acc.z = fmaf(p0, L0.z, fmaf(p1, L1.z, acc.z));
        acc.w = fmaf(p0, L0.w, fmaf(p1, L1.w, acc.w));
    }
    if (i < re) {
        int s0 = g_esrc[i];
        float2 ea0 = g_eea[i];
        float4 L0 = ((const float4*)(g_xl2 + (long)s0 * C2))[lane];
        float part0 = lrelu_dot(L0, R, ea0.x, ea0.y, W0, W1_, A);
#pragma unroll
        for (int o = 16; o > 0; o >>= 1) part0 += __shfl_xor_sync(0xffffffffu, part0, o);
        float p0 = __expf(part0);
        den += p0;
        acc.x = fmaf(p0, L0.x, acc.x); acc.y = fmaf(p0, L0.y, acc.y);
        acc.z = fmaf(p0, L0.z, acc.z); acc.w = fmaf(p0, L0.w, acc.w);
    }
    float inv = 1.f / den;
    float4 bb = __ldg((const float4*)b2 + lane);
    float v0 = acc.x * inv + bb.x; v0 = v0 > 0.f ? v0 : (__expf(v0) - 1.f);
    float v1 = acc.y * inv + bb.y; v1 = v1 > 0.f ? v1 : (__expf(v1) - 1.f);
    float v2 = acc.z * inv + bb.z; v2 = v2 > 0.f ? v2 : (__expf(v2) - 1.f);
    float v3 = acc.w * inv + bb.w; v3 = v3 > 0.f ? v3 : (__expf(v3) - 1.f);
    float4 wA = __ldg((const float4*)Wfc + 2 * lane);
    float4 wB = __ldg((const float4*)Wfc + 2 * lane + 1);
    float o0 = v0 * wA.x + v1 * wA.z + v2 * wB.x + v3 * wB.z;
    float o1 = v0 * wA.y + v1 * wA.w + v2 * wB.y + v3 * wB.w;
#pragma unroll
    for (int o = 16; o > 0; o >>= 1) {
        o0 += __shfl_xor_sync(0xffffffffu, o0, o);
        o1 += __shfl_xor_sync(0xffffffffu, o1, o);
    }
    if (lane == 0) {
        out[2 * node]     = o0 + __ldg(bfc);
        out[2 * node + 1] = o1 + __ldg(bfc + 1);
    }
}

// ---------------- launch ----------------
extern "C" void kernel_launch(void* const* d_in, const int* in_sizes, int n_in,
                              void* d_out, int out_size) {
    const float* x    = (const float*)d_in[0];
    const int*   ei   = (const int*)  d_in[1];
    const float* ea   = (const float*)d_in[2];
    const int*   rt   = (const int*)  d_in[3];
    const float* aaem = (const float*)d_in[4];
    const float* W1l  = (const float*)d_in[5];
    const float* W1r  = (const float*)d_in[6];
    const float* W1e  = (const float*)d_in[7];
    const float* att1 = (const float*)d_in[8];
    const float* b1   = (const float*)d_in[9];
    const float* W2l  = (const float*)d_in[10];
    const float* W2r  = (const float*)d_in[11];
    const float* W2e  = (const float*)d_in[12];
    const float* att2 = (const float*)d_in[13];
    const float* b2   = (const float*)d_in[14];
    const float* Wfc  = (const float*)d_in[15];
    const float* bfc  = (const float*)d_in[16];
    float* out = (float*)d_out;

    int N = in_sizes[0] / 5;
    int E = in_sizes[1] / 2;
    if (N > MAXN) N = MAXN;
    if (E > MAXE) E = MAXE;
    const int* src = ei;
    const int* dst = ei + E;
    int NP_BLK = (N + 63) / 64;
    int nb = (N + 1023) / 1024;

    k_h0<<<(N * TOTINP + 255) / 256, 256>>>(x, rt, aaem, N);
    k_deg<<<(E + 255) / 256, 256>>>(dst, ea, E);
    k_scan1<<<nb, 1024>>>(N);
    k_scan3<<<(N + 255) / 256, 256>>>(N, nb);
    k_scatter<<<(E + 255) / 256, 256>>>(src, dst, ea, E);

    k_gemm1<<<dim3(NP_BLK, 4, 2), 256>>>(W1l, W1r, N);
    k_edge1<<<N, 128>>>(W1e, att1, b1, N);

    k_gemm2<<<dim3(NP_BLK, 1, 2), 256>>>(W2l, W2r, N);
    k_edge2<<<(N + 7) / 8, 256>>>(W2e, att2, b2, Wfc, bfc, out, N);
}

// round 10
// speedup vs baseline: 1.9612x; 1.1658x over previous
#include <cuda_runtime.h>
#include <cuda_fp16.h>
#include <mma.h>
#include <math.h>
#include <float.h>

using namespace nvcuda;

#define MAXN 20000
#define MAXNP 20032
#define MAXE 150000
#define TOTINP 40
#define C1 512
#define H1 4
#define C2 128

// ---------------- scratch ----------------
static __device__ float  g_h0[MAXNP * TOTINP];
static __device__ __half g_xl1h[MAXNP * C1];   // gather-side features, fp16
static __device__ float  g_xr1[MAXNP * C1];
static __device__ float  g_h1[MAXNP * C1];
static __device__ __half g_xl2h[MAXNP * C2];
static __device__ float  g_xr2[MAXNP * C2];
static __device__ float  g_easum[MAXN * 2];
static __device__ float  g_loopea[MAXN * 2];
static __device__ int    g_deg[MAXN];
static __device__ int    g_rowstart[MAXN + 1];
static __device__ int    g_cursor[MAXN];
static __device__ int    g_esrc[MAXE];         // src permuted into CSR order
static __device__ float2 g_eea[MAXE];          // edge_attr permuted into CSR order
static __device__ int    g_blocksum[32];

// ---------------- init + h0 = concat(x, aa_emb[residue_type]) ----------------
__global__ void k_h0(const float* __restrict__ x, const int* __restrict__ rt,
                     const float* __restrict__ aaemb, int N) {
    int i = blockIdx.x * blockDim.x + threadIdx.x;
    if (i < N) {
        g_deg[i] = 0;
        g_cursor[i] = 0;
        g_easum[2 * i] = 0.f;
        g_easum[2 * i + 1] = 0.f;
    }
    if (i >= N * TOTINP) return;
    int n = i / TOTINP, c = i - n * TOTINP;
    float v = 0.f;
    if (c < 5) v = x[n * 5 + c];
    else if (c < 37) v = aaemb[rt[n] * 32 + (c - 5)];
    g_h0[i] = v;
}

// ---------------- degree + edge-attr sums ----------------
__global__ void k_deg(const int* __restrict__ dst, const float* __restrict__ ea, int E) {
    int e = blockIdx.x * blockDim.x + threadIdx.x;
    if (e >= E) return;
    int d = dst[e];
    float2 a = ((const float2*)ea)[e];
    atomicAdd(&g_deg[d], 1);
    atomicAdd(&g_easum[2 * d], a.x);
    atomicAdd(&g_easum[2 * d + 1], a.y);
}

// ---------------- parallel scan ----------------
__global__ void k_scan1(int N) {
    __shared__ int sm[1024];
    int i = blockIdx.x * 1024 + threadIdx.x;
    int v = (i < N) ? g_deg[i] : 0;
    sm[threadIdx.x] = v;
    __syncthreads();
    for (int o = 1; o < 1024; o <<= 1) {
        int t = (threadIdx.x >= o) ? sm[threadIdx.x - o] : 0;
        __syncthreads();
        sm[threadIdx.x] += t;
        __syncthreads();
    }
    if (i < N) g_rowstart[i] = sm[threadIdx.x] - v;
    if (threadIdx.x == 1023) g_blocksum[blockIdx.x] = sm[1023];
}
__global__ void k_scan3(int N, int nb) {
    __shared__ int soff[32];
    int t = threadIdx.x;
    if (t < 32) {
        int v = (t < nb) ? g_blocksum[t] : 0;
        int s = v;
#pragma unroll
        for (int o = 1; o < 32; o <<= 1) {
            int u = __shfl_up_sync(0xffffffffu, s, o);
            if (t >= o) s += u;
        }
        soff[t] = s - v;
    }
    __syncthreads();
    int i = blockIdx.x * blockDim.x + t;
    if (i < N) {
        g_rowstart[i] += soff[i >> 10];
        int dg = g_deg[i];
        float fd = (dg < 1) ? 1.f : (float)dg;
        g_loopea[2 * i]     = g_easum[2 * i] / fd;
        g_loopea[2 * i + 1] = g_easum[2 * i + 1] / fd;
    }
    if (i == 0) g_rowstart[N] = soff[31];
}

__global__ void k_scatter(const int* __restrict__ src, const int* __restrict__ dst,
                          const float* __restrict__ ea, int E) {
    int e = blockIdx.x * blockDim.x + threadIdx.x;
    if (e >= E) return;
    int d = dst[e];
    int pos = g_rowstart[d] + atomicAdd(&g_cursor[d], 1);
    g_esrc[pos] = src[e];
    g_eea[pos] = ((const float2*)ea)[e];
}

// ---- epilogue helper: warp writes one 16x16 fp32 tile (ldm=16) as fp16 (16B stores) ----
__device__ __forceinline__ void tile_to_half(const float* st, __half* gbase,
                                             long grow0, int gcol0, int ldg_, int lane) {
    int row = lane >> 1, colh = (lane & 1) * 8;
    const float* sp = st + row * 16 + colh;
    __half2 h0 = __floats2half2_rn(sp[0], sp[1]);
    __half2 h1 = __floats2half2_rn(sp[2], sp[3]);
    __half2 h2 = __floats2half2_rn(sp[4], sp[5]);
    __half2 h3 = __floats2half2_rn(sp[6], sp[7]);
    uint4 u = make_uint4(*(unsigned*)&h0, *(unsigned*)&h1, *(unsigned*)&h2, *(unsigned*)&h3);
    *(uint4*)(gbase + (grow0 + row) * ldg_ + gcol0 + colh) = u;
}

// ---------------- layer-1 GEMM (tf32 WMMA): [NP,40] @ [40,512] ----------------
// z=0 -> fp16 xl1h, z=1 -> fp32 xr1
__global__ void __launch_bounds__(256) k_gemm1(const float* __restrict__ Wl,
                                               const float* __restrict__ Wr, int N) {
    const float* W = blockIdx.z ? Wr : Wl;
    __shared__ float As[64 * 44];
    __shared__ float Bs[40 * 132];
    __shared__ float stg[8 * 256];       // per-warp 16x16 staging, ldm=16 (valid: 64B)
    int tid = threadIdx.x;
    int n0 = blockIdx.x * 64;
    int col0 = blockIdx.y * 128;
    for (int idx = tid; idx < 64 * 40; idx += 256) {
        int r = idx / 40, c = idx - r * 40;
        float v = (n0 + r < N) ? g_h0[(n0 + r) * TOTINP + c] : 0.f;
        As[r * 44 + c] = wmma::__float_to_tf32(v);
    }
    for (int idx = tid; idx < 40 * 128; idx += 256) {
        int r = idx >> 7, c = idx & 127;
        float v = (r < 37) ? W[r * C1 + col0 + c] : 0.f;
        Bs[r * 132 + c] = wmma::__float_to_tf32(v);
    }
    __syncthreads();
    int wid = tid >> 5, lane = tid & 31;
    int wr = wid & 1, wc = wid >> 1;
    wmma::fragment<wmma::accumulator, 16, 16, 8, float> acc[2][2];
#pragma unroll
    for (int i = 0; i < 2; i++)
#pragma unroll
        for (int j = 0; j < 2; j++) wmma::fill_fragment(acc[i][j], 0.f);
#pragma unroll
    for (int k0 = 0; k0 < 40; k0 += 8) {
        wmma::fragment<wmma::matrix_a, 16, 16, 8, wmma::precision::tf32, wmma::row_major> a[2];
        wmma::fragment<wmma::matrix_b, 16, 16, 8, wmma::precision::tf32, wmma::row_major> b[2];
#pragma unroll
        for (int i = 0; i < 2; i++)
            wmma::load_matrix_sync(a[i], &As[(wr * 32 + i * 16) * 44 + k0], 44);
#pragma unroll
        for (int j = 0; j < 2; j++)
            wmma::load_matrix_sync(b[j], &Bs[k0 * 132 + wc * 32 + j * 16], 132);
#pragma unroll
        for (int i = 0; i < 2; i++)
#pragma unroll
            for (int j = 0; j < 2; j++)
                wmma::mma_sync(acc[i][j], a[i], b[j], acc[i][j]);
    }
    if (blockIdx.z) {
#pragma unroll
        for (int i = 0; i < 2; i++)
#pragma unroll
            for (int j = 0; j < 2; j++)
                wmma::store_matrix_sync(&g_xr1[(n0 + wr * 32 + i * 16) * C1 + col0 + wc * 32 + j * 16],
                                        acc[i][j], C1, wmma::mem_row_major);
    } else {
        float* st = stg + wid * 256;
#pragma unroll
        for (int i = 0; i < 2; i++)
#pragma unroll
            for (int j = 0; j < 2; j++) {
                wmma::store_matrix_sync(st, acc[i][j], 16, wmma::mem_row_major);
                __syncwarp();
                tile_to_half(st, g_xl1h, n0 + wr * 32 + i * 16,
                             col0 + wc * 32 + j * 16, C1, lane);
                __syncwarp();
            }
    }
}

// ---------------- layer-2 GEMM (tf32 WMMA): [NP,512] @ [512,128] ----------------
__global__ void __launch_bounds__(256) k_gemm2(const float* __restrict__ Wl,
                                               const float* __restrict__ Wr, int N) {
    const float* W = blockIdx.z ? Wr : Wl;
    __shared__ float As[64 * 36];
    __shared__ float Bs[32 * 132];
    __shared__ float stg[8 * 256];
    int tid = threadIdx.x;
    int n0 = blockIdx.x * 64;
    int wid = tid >> 5, lane = tid & 31;
    int wr = wid & 1, wc = wid >> 1;
    wmma::fragment<wmma::accumulator, 16, 16, 8, float> acc[2][2];
#pragma unroll
    for (int i = 0; i < 2; i++)
#pragma unroll
        for (int j = 0; j < 2; j++) wmma::fill_fragment(acc[i][j], 0.f);
    for (int k0 = 0; k0 < C1; k0 += 32) {
        for (int idx = tid; idx < 64 * 32; idx += 256) {
            int r = idx >> 5, c = idx & 31;
            float v = (n0 + r < N) ? g_h1[(n0 + r) * C1 + k0 + c] : 0.f;
            As[r * 36 + c] = wmma::__float_to_tf32(v);
        }
        for (int idx = tid; idx < 32 * 128; idx += 256) {
            int r = idx >> 7, c = idx & 127;
            Bs[r * 132 + c] = wmma::__float_to_tf32(W[(k0 + r) * C2 + c]);
        }
        __syncthreads();
#pragma unroll
        for (int kk = 0; kk < 32; kk += 8) {
            wmma::fragment<wmma::matrix_a, 16, 16, 8, wmma::precision::tf32, wmma::row_major> a[2];
            wmma::fragment<wmma::matrix_b, 16, 16, 8, wmma::precision::tf32, wmma::row_major> b[2];
#pragma unroll
            for (int i = 0; i < 2; i++)
                wmma::load_matrix_sync(a[i], &As[(wr * 32 + i * 16) * 36 + kk], 36);
#pragma unroll
            for (int j = 0; j < 2; j++)
                wmma::load_matrix_sync(b[j], &Bs[kk * 132 + wc * 32 + j * 16], 132);
#pragma unroll
            for (int i = 0; i < 2; i++)
#pragma unroll
                for (int j = 0; j < 2; j++)
                    wmma::mma_sync(acc[i][j], a[i], b[j], acc[i][j]);
        }
        __syncthreads();
    }
    if (blockIdx.z) {
#pragma unroll
        for (int i = 0; i < 2; i++)
#pragma unroll
            for (int j = 0; j < 2; j++)
                wmma::store_matrix_sync(&g_xr2[(n0 + wr * 32 + i * 16) * C2 + wc * 32 + j * 16],
                                        acc[i][j], C2, wmma::mem_row_major);
    } else {
        float* st = stg + wid * 256;
#pragma unroll
        for (int i = 0; i < 2; i++)
#pragma unroll
            for (int j = 0; j < 2; j++) {
                wmma::store_matrix_sync(st, acc[i][j], 16, wmma::mem_row_major);
                __syncwarp();
                tile_to_half(st, g_xl2h, n0 + wr * 32 + i * 16,
                             wc * 32 + j * 16, C2, lane);
                __syncwarp();
            }
    }
}

// ---- helpers ----
__device__ __forceinline__ float4 ld_half4(const __half* base, int idx4) {
    uint2 u = __ldg((const uint2*)base + idx4);
    __half2 ha = *(__half2*)&u.x, hb = *(__half2*)&u.y;
    float2 fa = __half22float2(ha), fb = __half22float2(hb);
    return make_float4(fa.x, fa.y, fb.x, fb.y);
}
__device__ __forceinline__ float lrelu_dot(float4 L, float4 R, float e0, float e1,
                                           float4 W0, float4 W1_, float4 A) {
    float zx = L.x + R.x + e0 * W0.x + e1 * W1_.x; zx = zx > 0.f ? zx : 0.2f * zx;
    float zy = L.y + R.y + e0 * W0.y + e1 * W1_.y; zy = zy > 0.f ? zy : 0.2f * zy;
    float zz = L.z + R.z + e0 * W0.z + e1 * W1_.z; zz = zz > 0.f ? zz : 0.2f * zz;
    float zw = L.w + R.w + e0 * W0.w + e1 * W1_.w; zw = zw > 0.f ? zw : 0.2f * zw;
    return A.x * zx + A.y * zy + A.z * zz + A.w * zw;
}

// ---------------- layer-1 SINGLE-PASS fused attention+aggregation ----------------
__global__ void __launch_bounds__(128) k_edge1(const float* __restrict__ W1e,
                                               const float* __restrict__ att,
                                               const float* __restrict__ b1, int N) {
    int d = blockIdx.x;
    int lane = threadIdx.x & 31, h = threadIdx.x >> 5;
    int c4 = h * 32 + lane;
    float4 R  = ((const float4*)(g_xr1 + (long)d * C1))[c4];
    float4 W0 = __ldg((const float4*)W1e + c4);
    float4 W1_ = __ldg((const float4*)(W1e + C1) + c4);
    float4 A  = __ldg((const float4*)att + c4);
    int rs = g_rowstart[d], re = g_rowstart[d + 1];
    float den;
    float4 acc;
    {   // self loop
        float e0 = g_loopea[2 * d], e1 = g_loopea[2 * d + 1];
        float4 L = ld_half4(g_xl1h + (long)d * C1, c4);
        float part = lrelu_dot(L, R, e0, e1, W0, W1_, A);
#pragma unroll
        for (int o = 16; o > 0; o >>= 1) part += __shfl_xor_sync(0xffffffffu, part, o);
        float p = __expf(part);
        den = p;
        acc.x = p * L.x; acc.y = p * L.y; acc.z = p * L.z; acc.w = p * L.w;
    }
    int i = rs;
    for (; i + 4 <= re; i += 4) {
        int s0 = g_esrc[i], s1 = g_esrc[i + 1], s2 = g_esrc[i + 2], s3 = g_esrc[i + 3];
        float2 ea0 = g_eea[i], ea1 = g_eea[i + 1], ea2 = g_eea[i + 2], ea3 = g_eea[i + 3];
        float4 L0 = ld_half4(g_xl1h + (long)s0 * C1, c4);
        float4 L1 = ld_half4(g_xl1h + (long)s1 * C1, c4);
        float4 L2 = ld_half4(g_xl1h + (long)s2 * C1, c4);
        float4 L3 = ld_half4(g_xl1h + (long)s3 * C1, c4);
        float p0 = lrelu_dot(L0, R, ea0.x, ea0.y, W0, W1_, A);
        float p1 = lrelu_dot(L1, R, ea1.x, ea1.y, W0, W1_, A);
        float p2 = lrelu_dot(L2, R, ea2.x, ea2.y, W0, W1_, A);
        float p3 = lrelu_dot(L3, R, ea3.x, ea3.y, W0, W1_, A);
#pragma unroll
        for (int o = 16; o > 0; o >>= 1) {
            p0 += __shfl_xor_sync(0xffffffffu, p0, o);
            p1 += __shfl_xor_sync(0xffffffffu, p1, o);
            p2 += __shfl_xor_sync(0xffffffffu, p2, o);
            p3 += __shfl_xor_sync(0xffffffffu, p3, o);
        }
        p0 = __expf(p0); p1 = __expf(p1); p2 = __expf(p2); p3 = __expf(p3);
        den += (p0 + p1) + (p2 + p3);
        acc.x = fmaf(p0, L0.x, fmaf(p1, L1.x, fmaf(p2, L2.x, fmaf(p3, L3.x, acc.x))));
        acc.y = fmaf(p0, L0.y, fmaf(p1, L1.y, fmaf(p2, L2.y, fmaf(p3, L3.y, acc.y))));
        acc.z = fmaf(p0, L0.z, fmaf(p1, L1.z, fmaf(p2, L2.z, fmaf(p3, L3.z, acc.z))));
        acc.w = fmaf(p0, L0.w, fmaf(p1, L1.w, fmaf(p2, L2.w, fmaf(p3, L3.w, acc.w))));
    }
    for (; i < re; i++) {
        int s0 = g_esrc[i];
        float2 ea0 = g_eea[i];
        float4 L0 = ld_half4(g_xl1h + (long)s0 * C1, c4);
        float p0 = lrelu_dot(L0, R, ea0.x, ea0.y, W0, W1_, A);
#pragma unroll
        for (int o = 16; o > 0; o >>= 1) p0 += __shfl_xor_sync(0xffffffffu, p0, o);
        p0 = __expf(p0);
        den += p0;
        acc.x = fmaf(p0, L0.x, acc.x); acc.y = fmaf(p0, L0.y, acc.y);
        acc.z = fmaf(p0, L0.z, acc.z); acc.w = fmaf(p0, L0.w, acc.w);
    }
    float inv = 1.f / den;
    float4 bb = __ldg((const float4*)b1 + c4);
    float v0 = acc.x * inv + bb.x; v0 = v0 > 0.f ? v0 : (__expf(v0) - 1.f);
    float v1 = acc.y * inv + bb.y; v1 = v1 > 0.f ? v1 : (__expf(v1) - 1.f);
    float v2 = acc.z * inv + bb.z; v2 = v2 > 0.f ? v2 : (__expf(v2) - 1.f);
    float v3 = acc.w * inv + bb.w; v3 = v3 > 0.f ? v3 : (__expf(v3) - 1.f);
    ((float4*)(g_h1 + (long)d * C1))[c4] = make_float4(v0, v1, v2, v3);
}

// ---------------- layer-2 SINGLE-PASS fused att+agg+ELU+FC: warp per node ----------------
__global__ void __launch_bounds__(256) k_edge2(const float* __restrict__ W2e,
                                               const float* __restrict__ att2,
                                               const float* __restrict__ b2,
                                               const float* __restrict__ Wfc,
                                               const float* __restrict__ bfc,
                                               float* __restrict__ out, int N) {
    int w = threadIdx.x >> 5, lane = threadIdx.x & 31;
    int node = blockIdx.x * 8 + w;
    if (node >= N) return;
    float4 R  = ((const float4*)(g_xr2 + (long)node * C2))[lane];
    float4 W0 = __ldg((const float4*)W2e + lane);
    float4 W1_ = __ldg((const float4*)(W2e + C2) + lane);
    float4 A  = __ldg((const float4*)att2 + lane);
    int rs = g_rowstart[node], re = g_rowstart[node + 1];
    float den;
    float4 acc;
    {
        float e0 = g_loopea[2 * node], e1 = g_loopea[2 * node + 1];
        float4 L = ld_half4(g_xl2h + (long)node * C2, lane);
        float part = lrelu_dot(L, R, e0, e1, W0, W1_, A);
#pragma unroll
        for (int o = 16; o > 0; o >>= 1) part += __shfl_xor_sync(0xffffffffu, part, o);
        float p = __expf(part);
        den = p;
        acc.x = p * L.x; acc.y = p * L.y; acc.z = p * L.z; acc.w = p * L.w;
    }
    int i = rs;
    for (; i + 4 <= re; i += 4) {
        int s0 = g_esrc[i], s1 = g_esrc[i + 1], s2 = g_esrc[i + 2], s3 = g_esrc[i + 3];
        float2 ea0 = g_eea[i], ea1 = g_eea[i + 1], ea2 = g_eea[i + 2], ea3 = g_eea[i + 3];
        float4 L0 = ld_half4(g_xl2h + (long)s0 * C2, lane);
        float4 L1 = ld_half4(g_xl2h + (long)s1 * C2, lane);
        float4 L2 = ld_half4(g_xl2h + (long)s2 * C2, lane);
        float4 L3 = ld_half4(g_xl2h + (long)s3 * C2, lane);
        float p0 = lrelu_dot(L0, R, ea0.x, ea0.y, W0, W1_, A);
        float p1 = lrelu_dot(L1, R, ea1.x, ea1.y, W0, W1_, A);
        float p2 = lrelu_dot(L2, R, ea2.x, ea2.y, W0, W1_, A);
        float p3 = lrelu_dot(L3, R, ea3.x, ea3.y, W0, W1_, A);
#pragma unroll
        for (int o = 16; o > 0; o >>= 1) {
            p0 += __shfl_xor_sync(0xffffffffu, p0, o);
            p1 += __shfl_xor_sync(0xffffffffu, p1, o);
            p2 += __shfl_xor_sync(0xffffffffu, p2, o);
            p3 += __shfl_xor_sync(0xffffffffu, p3, o);
        }
        p0 = __expf(p0); p1 = __expf(p1); p2 = __expf(p2); p3 = __expf(p3);
        den += (p0 + p1) + (p2 + p3);
        acc.x = fmaf(p0, L0.x, fmaf(p1, L1.x, fmaf(p2, L2.x, fmaf(p3, L3.x, acc.x))));
        acc.y = fmaf(p0, L0.y, fmaf(p1, L1.y, fmaf(p2, L2.y, fmaf(p3, L3.y, acc.y))));
        acc.z = fmaf(p0, L0.z, fmaf(p1, L1.z, fmaf(p2, L2.z, fmaf(p3, L3.z, acc.z))));
        acc.w = fmaf(p0, L0.w, fmaf(p1, L1.w, fmaf(p2, L2.w, fmaf(p3, L3.w, acc.w))));
    }
    for (; i < re; i++) {
        int s0 = g_esrc[i];
        float2 ea0 = g_eea[i];
        float4 L0 = ld_half4(g_xl2h + (long)s0 * C2, lane);
        float p0 = lrelu_dot(L0, R, ea0.x, ea0.y, W0, W1_, A);
#pragma unroll
        for (int o = 16; o > 0; o >>= 1) p0 += __shfl_xor_sync(0xffffffffu, p0, o);
        p0 = __expf(p0);
        den += p0;
        acc.x = fmaf(p0, L0.x, acc.x); acc.y = fmaf(p0, L0.y, acc.y);
        acc.z = fmaf(p0, L0.z, acc.z); acc.w = fmaf(p0, L0.w, acc.w);
    }
    float inv = 1.f / den;
    float4 bb = __ldg((const float4*)b2 + lane);
    float v0 = acc.x * inv + bb.x; v0 = v0 > 0.f ? v0 : (__expf(v0) - 1.f);
    float v1 = acc.y * inv + bb.y; v1 = v1 > 0.f ? v1 : (__expf(v1) - 1.f);
    float v2 = acc.z * inv + bb.z; v2 = v2 > 0.f ? v2 : (__expf(v2) - 1.f);
    float v3 = acc.w * inv + bb.w; v3 = v3 > 0.f ? v3 : (__expf(v3) - 1.f);
    float4 wA = __ldg((const float4*)Wfc + 2 * lane);
    float4 wB = __ldg((const float4*)Wfc + 2 * lane + 1);
    float o0 = v0 * wA.x + v1 * wA.z + v2 * wB.x + v3 * wB.z;
    float o1 = v0 * wA.y + v1 * wA.w + v2 * wB.y + v3 * wB.w;
#pragma unroll
    for (int o = 16; o > 0; o >>= 1) {
        o0 += __shfl_xor_sync(0xffffffffu, o0, o);
        o1 += __shfl_xor_sync(0xffffffffu, o1, o);
    }
    if (lane == 0) {
        out[2 * node]     = o0 + __ldg(bfc);
        out[2 * node + 1] = o1 + __ldg(bfc + 1);
    }
}

// ---------------- launch ----------------
extern "C" void kernel_launch(void* const* d_in, const int* in_sizes, int n_in,
                              void* d_out, int out_size) {
    const float* x    = (const float*)d_in[0];
    const int*   ei   = (const int*)  d_in[1];
    const float* ea   = (const float*)d_in[2];
    const int*   rt   = (const int*)  d_in[3];
    const float* aaem = (const float*)d_in[4];
    const float* W1l  = (const float*)d_in[5];
    const float* W1r  = (const float*)d_in[6];
    const float* W1e  = (const float*)d_in[7];
    const float* att1 = (const float*)d_in[8];
    const float* b1   = (const float*)d_in[9];
    const float* W2l  = (const float*)d_in[10];
    const float* W2r  = (const float*)d_in[11];
    const float* W2e  = (const float*)d_in[12];
    const float* att2 = (const float*)d_in[13];
    const float* b2   = (const float*)d_in[14];
    const float* Wfc  = (const float*)d_in[15];
    const float* bfc  = (const float*)d_in[16];
    float* out = (float*)d_out;

    int N = in_sizes[0] / 5;
    int E = in_sizes[1] / 2;
    if (N > MAXN) N = MAXN;
    if (E > MAXE) E = MAXE;
    const int* src = ei;
    const int* dst = ei + E;
    int NP_BLK = (N + 63) / 64;
    int nb = (N + 1023) / 1024;

    k_h0<<<(N * TOTINP + 255) / 256, 256>>>(x, rt, aaem, N);
    k_deg<<<(E + 255) / 256, 256>>>(dst, ea, E);
    k_scan1<<<nb, 1024>>>(N);
    k_scan3<<<(N + 255) / 256, 256>>>(N, nb);
    k_scatter<<<(E + 255) / 256, 256>>>(src, dst, ea, E);

    k_gemm1<<<dim3(NP_BLK, 4, 2), 256>>>(W1l, W1r, N);
    k_edge1<<<N, 128>>>(W1e, att1, b1, N);

    k_gemm2<<<dim3(NP_BLK, 1, 2), 256>>>(W2l, W2r, N);
    k_edge2<<<(N + 7) / 8, 256>>>(W2e, att2, b2, Wfc, bfc, out, N);
}

// round 11
// speedup vs baseline: 2.5769x; 1.3139x over previous
#include <cuda_runtime.h>
#include <cuda_fp16.h>
#include <mma.h>
#include <math.h>
#include <float.h>

using namespace nvcuda;

#define MAXN 20000
#define MAXNP 20032
#define MAXE 150000
#define C1 512
#define H1 4
#define C2 128

// ---------------- scratch ----------------
static __device__ __half g_xl1h[MAXNP * C1];   // gather-side features, fp16
static __device__ float  g_xr1[MAXNP * C1];
static __device__ __half g_h1h[MAXNP * C1];    // layer-1 output, fp16 (gemm2 A operand)
static __device__ __half g_xl2h[MAXNP * C2];
static __device__ float  g_xr2[MAXNP * C2];
static __device__ float  g_easum[MAXN * 2];
static __device__ float  g_loopea[MAXN * 2];
static __device__ int    g_deg[MAXN];
static __device__ int    g_rowstart[MAXN + 1];
static __device__ int    g_cursor[MAXN];
static __device__ int    g_esrc[MAXE];         // src permuted into CSR order
static __device__ float2 g_eea[MAXE];          // edge_attr permuted into CSR order
static __device__ int    g_blocksum[32];

// ---------------- per-node init ----------------
__global__ void k_init(int N) {
    int i = blockIdx.x * blockDim.x + threadIdx.x;
    if (i >= N) return;
    g_deg[i] = 0;
    g_cursor[i] = 0;
    g_easum[2 * i] = 0.f;
    g_easum[2 * i + 1] = 0.f;
}

// ---------------- degree + edge-attr sums ----------------
__global__ void k_deg(const int* __restrict__ dst, const float* __restrict__ ea, int E) {
    int e = blockIdx.x * blockDim.x + threadIdx.x;
    if (e >= E) return;
    int d = dst[e];
    float2 a = ((const float2*)ea)[e];
    atomicAdd(&g_deg[d], 1);
    atomicAdd(&g_easum[2 * d], a.x);
    atomicAdd(&g_easum[2 * d + 1], a.y);
}

// ---------------- parallel scan ----------------
__global__ void k_scan1(int N) {
    __shared__ int sm[1024];
    int i = blockIdx.x * 1024 + threadIdx.x;
    int v = (i < N) ? g_deg[i] : 0;
    sm[threadIdx.x] = v;
    __syncthreads();
    for (int o = 1; o < 1024; o <<= 1) {
        int t = (threadIdx.x >= o) ? sm[threadIdx.x - o] : 0;
        __syncthreads();
        sm[threadIdx.x] += t;
        __syncthreads();
    }
    if (i < N) g_rowstart[i] = sm[threadIdx.x] - v;
    if (threadIdx.x == 1023) g_blocksum[blockIdx.x] = sm[1023];
}
__global__ void k_scan3(int N, int nb) {
    __shared__ int soff[32];
    int t = threadIdx.x;
    if (t < 32) {
        int v = (t < nb) ? g_blocksum[t] : 0;
        int s = v;
#pragma unroll
        for (int o = 1; o < 32; o <<= 1) {
            int u = __shfl_up_sync(0xffffffffu, s, o);
            if (t >= o) s += u;
        }
        soff[t] = s - v;
    }
    __syncthreads();
    int i = blockIdx.x * blockDim.x + t;
    if (i < N) {
        g_rowstart[i] += soff[i >> 10];
        int dg = g_deg[i];
        float fd = (dg < 1) ? 1.f : (float)dg;
        g_loopea[2 * i]     = g_easum[2 * i] / fd;
        g_loopea[2 * i + 1] = g_easum[2 * i + 1] / fd;
    }
    if (i == 0) g_rowstart[N] = soff[31];
}

__global__ void k_scatter(const int* __restrict__ src, const int* __restrict__ dst,
                          const float* __restrict__ ea, int E) {
    int e = blockIdx.x * blockDim.x + threadIdx.x;
    if (e >= E) return;
    int d = dst[e];
    int pos = g_rowstart[d] + atomicAdd(&g_cursor[d], 1);
    g_esrc[pos] = src[e];
    g_eea[pos] = ((const float2*)ea)[e];
}

// ---- epilogue helper: warp writes one 16x16 fp32 tile (ldm=16) as fp16 (16B stores) ----
__device__ __forceinline__ void tile_to_half(const float* st, __half* gbase,
                                             long grow0, int gcol0, int ldg_, int lane) {
    int row = lane >> 1, colh = (lane & 1) * 8;
    const float* sp = st + row * 16 + colh;
    __half2 h0 = __floats2half2_rn(sp[0], sp[1]);
    __half2 h1 = __floats2half2_rn(sp[2], sp[3]);
    __half2 h2 = __floats2half2_rn(sp[4], sp[5]);
    __half2 h3 = __floats2half2_rn(sp[6], sp[7]);
    uint4 u = make_uint4(*(unsigned*)&h0, *(unsigned*)&h1, *(unsigned*)&h2, *(unsigned*)&h3);
    *(uint4*)(gbase + (grow0 + row) * ldg_ + gcol0 + colh) = u;
}

// ---------------- layer-1 GEMM (tf32 WMMA): concat(x, aa_emb[rt]) @ [40,512] ----------------
// h0 concat fused into the A-tile load. z=0 -> fp16 xl1h, z=1 -> fp32 xr1
__global__ void __launch_bounds__(256) k_gemm1(const float* __restrict__ x,
                                               const int* __restrict__ rt,
                                               const float* __restrict__ aaemb,
                                               const float* __restrict__ Wl,
                                               const float* __restrict__ Wr, int N) {
    const float* W = blockIdx.z ? Wr : Wl;
    __shared__ float As[64 * 44];
    __shared__ float Bs[40 * 132];
    __shared__ float stg[8 * 256];       // per-warp 16x16 staging, ldm=16
    int tid = threadIdx.x;
    int n0 = blockIdx.x * 64;
    int col0 = blockIdx.y * 128;
    for (int idx = tid; idx < 64 * 40; idx += 256) {
        int r = idx / 40, c = idx - r * 40;
        int n = n0 + r;
        float v = 0.f;
        if (n < N) {
            if (c < 5) v = x[n * 5 + c];
            else if (c < 37) v = aaemb[rt[n] * 32 + (c - 5)];
        }
        As[r * 44 + c] = wmma::__float_to_tf32(v);
    }
    for (int idx = tid; idx < 40 * 128; idx += 256) {
        int r = idx >> 7, c = idx & 127;
        float v = (r < 37) ? W[r * C1 + col0 + c] : 0.f;
        Bs[r * 132 + c] = wmma::__float_to_tf32(v);
    }
    __syncthreads();
    int wid = tid >> 5, lane = tid & 31;
    int wr = wid & 1, wc = wid >> 1;
    wmma::fragment<wmma::accumulator, 16, 16, 8, float> acc[2][2];
#pragma unroll
    for (int i = 0; i < 2; i++)
#pragma unroll
        for (int j = 0; j < 2; j++) wmma::fill_fragment(acc[i][j], 0.f);
#pragma unroll
    for (int k0 = 0; k0 < 40; k0 += 8) {
        wmma::fragment<wmma::matrix_a, 16, 16, 8, wmma::precision::tf32, wmma::row_major> a[2];
        wmma::fragment<wmma::matrix_b, 16, 16, 8, wmma::precision::tf32, wmma::row_major> b[2];
#pragma unroll
        for (int i = 0; i < 2; i++)
            wmma::load_matrix_sync(a[i], &As[(wr * 32 + i * 16) * 44 + k0], 44);
#pragma unroll
        for (int j = 0; j < 2; j++)
            wmma::load_matrix_sync(b[j], &Bs[k0 * 132 + wc * 32 + j * 16], 132);
#pragma unroll
        for (int i = 0; i < 2; i++)
#pragma unroll
            for (int j = 0; j < 2; j++)
                wmma::mma_sync(acc[i][j], a[i], b[j], acc[i][j]);
    }
    if (blockIdx.z) {
#pragma unroll
        for (int i = 0; i < 2; i++)
#pragma unroll
            for (int j = 0; j < 2; j++)
                wmma::store_matrix_sync(&g_xr1[(n0 + wr * 32 + i * 16) * C1 + col0 + wc * 32 + j * 16],
                                        acc[i][j], C1, wmma::mem_row_major);
    } else {
        float* st = stg + wid * 256;
#pragma unroll
        for (int i = 0; i < 2; i++)
#pragma unroll
            for (int j = 0; j < 2; j++) {
                wmma::store_matrix_sync(st, acc[i][j], 16, wmma::mem_row_major);
                __syncwarp();
                tile_to_half(st, g_xl1h, n0 + wr * 32 + i * 16,
                             col0 + wc * 32 + j * 16, C1, lane);
                __syncwarp();
            }
    }
}

// ---------------- layer-2 GEMM (fp16 WMMA m16n16k16): h1h[NP,512] @ [512,128] ----------------
__global__ void __launch_bounds__(256) k_gemm2(const float* __restrict__ Wl,
                                               const float* __restrict__ Wr, int N) {
    const float* W = blockIdx.z ? Wr : Wl;
    __shared__ __half Ah[64 * 40];       // stride 40 halves = 80B (16B-multiple)
    __shared__ __half Bh[32 * 136];      // stride 136 halves = 272B (16B-multiple)
    __shared__ float stg[8 * 256];
    int tid = threadIdx.x;
    int n0 = blockIdx.x * 64;
    int wid = tid >> 5, lane = tid & 31;
    int wr = wid & 1, wc = wid >> 1;
    wmma::fragment<wmma::accumulator, 16, 16, 16, float> acc[2][2];
#pragma unroll
    for (int i = 0; i < 2; i++)
#pragma unroll
        for (int j = 0; j < 2; j++) wmma::fill_fragment(acc[i][j], 0.f);
    for (int k0 = 0; k0 < C1; k0 += 32) {
        {   // A: 64x32 halves, one uint4 (8 halves) per thread
            int r = tid >> 2, g = (tid & 3) * 8;
            uint4 u = make_uint4(0, 0, 0, 0);
            if (n0 + r < N)
                u = *(const uint4*)(g_h1h + (long)(n0 + r) * C1 + k0 + g);
            *(uint4*)(Ah + r * 40 + g) = u;
        }
        for (int idx = tid; idx < 32 * 128; idx += 256) {
            int r = idx >> 7, c = idx & 127;
            Bh[r * 136 + c] = __float2half(W[(k0 + r) * C2 + c]);
        }
        __syncthreads();
#pragma unroll
        for (int kk = 0; kk < 32; kk += 16) {
            wmma::fragment<wmma::matrix_a, 16, 16, 16, __half, wmma::row_major> a[2];
            wmma::fragment<wmma::matrix_b, 16, 16, 16, __half, wmma::row_major> b[2];
#pragma unroll
            for (int i = 0; i < 2; i++)
                wmma::load_matrix_sync(a[i], &Ah[(wr * 32 + i * 16) * 40 + kk], 40);
#pragma unroll
            for (int j = 0; j < 2; j++)
                wmma::load_matrix_sync(b[j], &Bh[kk * 136 + wc * 32 + j * 16], 136);
#pragma unroll
            for (int i = 0; i < 2; i++)
#pragma unroll
                for (int j = 0; j < 2; j++)
                    wmma::mma_sync(acc[i][j], a[i], b[j], acc[i][j]);
        }
        __syncthreads();
    }
    if (blockIdx.z) {
#pragma unroll
        for (int i = 0; i < 2; i++)
#pragma unroll
            for (int j = 0; j < 2; j++)
                wmma::store_matrix_sync(&g_xr2[(n0 + wr * 32 + i * 16) * C2 + wc * 32 + j * 16],
                                        acc[i][j], C2, wmma::mem_row_major);
    } else {
        float* st = stg + wid * 256;
#pragma unroll
        for (int i = 0; i < 2; i++)
#pragma unroll
            for (int j = 0; j < 2; j++) {
                wmma::store_matrix_sync(st, acc[i][j], 16, wmma::mem_row_major);
                __syncwarp();
                tile_to_half(st, g_xl2h, n0 + wr * 32 + i * 16,
                             wc * 32 + j * 16, C2, lane);
                __syncwarp();
            }
    }
}

// ---- helpers ----
__device__ __forceinline__ float4 ld_half4(const __half* base, int idx4) {
    uint2 u = __ldg((const uint2*)base + idx4);
    __half2 ha = *(__half2*)&u.x, hb = *(__half2*)&u.y;
    float2 fa = __half22float2(ha), fb = __half22float2(hb);
    return make_float4(fa.x, fa.y, fb.x, fb.y);
}
__device__ __forceinline__ float lrelu_dot(float4 L, float4 R, float e0, float e1,
                                           float4 W0, float4 W1_, float4 A) {
    float zx = L.x + R.x + e0 * W0.x + e1 * W1_.x; zx = zx > 0.f ? zx : 0.2f * zx;
    float zy = L.y + R.y + e0 * W0.y + e1 * W1_.y; zy = zy > 0.f ? zy : 0.2f * zy;
    float zz = L.z + R.z + e0 * W0.z + e1 * W1_.z; zz = zz > 0.f ? zz : 0.2f * zz;
    float zw = L.w + R.w + e0 * W0.w + e1 * W1_.w; zw = zw > 0.f ? zw : 0.2f * zw;
    return A.x * zx + A.y * zy + A.z * zz + A.w * zw;
}

// ---------------- layer-1 SINGLE-PASS fused attention+aggregation ----------------
__global__ void __launch_bounds__(128) k_edge1(const float* __restrict__ W1e,
                                               const float* __restrict__ att,
                                               const float* __restrict__ b1, int N) {
    int d = blockIdx.x;
    int lane = threadIdx.x & 31, h = threadIdx.x >> 5;
    int c4 = h * 32 + lane;
    float4 R  = ((const float4*)(g_xr1 + (long)d * C1))[c4];
    float4 W0 = __ldg((const float4*)W1e + c4);
    float4 W1_ = __ldg((const float4*)(W1e + C1) + c4);
    float4 A  = __ldg((const float4*)att + c4);
    int rs = g_rowstart[d], re = g_rowstart[d + 1];
    float den;
    float4 acc;
    {   // self loop
        float e0 = g_loopea[2 * d], e1 = g_loopea[2 * d + 1];
        float4 L = ld_half4(g_xl1h + (long)d * C1, c4);
        float part = lrelu_dot(L, R, e0, e1, W0, W1_, A);
#pragma unroll
        for (int o = 16; o > 0; o >>= 1) part += __shfl_xor_sync(0xffffffffu, part, o);
        float p = __expf(part);
        den = p;
        acc.x = p * L.x; acc.y = p * L.y; acc.z = p * L.z; acc.w = p * L.w;
    }
    int i = rs;
    for (; i + 4 <= re; i += 4) {
        int s0 = g_esrc[i], s1 = g_esrc[i + 1], s2 = g_esrc[i + 2], s3 = g_esrc[i + 3];
        float2 ea0 = g_eea[i], ea1 = g_eea[i + 1], ea2 = g_eea[i + 2], ea3 = g_eea[i + 3];
        float4 L0 = ld_half4(g_xl1h + (long)s0 * C1, c4);
        float4 L1 = ld_half4(g_xl1h + (long)s1 * C1, c4);
        float4 L2 = ld_half4(g_xl1h + (long)s2 * C1, c4);
        float4 L3 = ld_half4(g_xl1h + (long)s3 * C1, c4);
        float p0 = lrelu_dot(L0, R, ea0.x, ea0.y, W0, W1_, A);
        float p1 = lrelu_dot(L1, R, ea1.x, ea1.y, W0, W1_, A);
        float p2 = lrelu_dot(L2, R, ea2.x, ea2.y, W0, W1_, A);
        float p3 = lrelu_dot(L3, R, ea3.x, ea3.y, W0, W1_, A);
#pragma unroll
        for (int o = 16; o > 0; o >>= 1) {
            p0 += __shfl_xor_sync(0xffffffffu, p0, o);
            p1 += __shfl_xor_sync(0xffffffffu, p1, o);
            p2 += __shfl_xor_sync(0xffffffffu, p2, o);
            p3 += __shfl_xor_sync(0xffffffffu, p3, o);
        }
        p0 = __expf(p0); p1 = __expf(p1); p2 = __expf(p2); p3 = __expf(p3);
        den += (p0 + p1) + (p2 + p3);
        acc.x = fmaf(p0, L0.x, fmaf(p1, L1.x, fmaf(p2, L2.x, fmaf(p3, L3.x, acc.x))));
        acc.y = fmaf(p0, L0.y, fmaf(p1, L1.y, fmaf(p2, L2.y, fmaf(p3, L3.y, acc.y))));
        acc.z = fmaf(p0, L0.z, fmaf(p1, L1.z, fmaf(p2, L2.z, fmaf(p3, L3.z, acc.z))));
        acc.w = fmaf(p0, L0.w, fmaf(p1, L1.w, fmaf(p2, L2.w, fmaf(p3, L3.w, acc.w))));
    }
    for (; i < re; i++) {
        int s0 = g_esrc[i];
        float2 ea0 = g_eea[i];
        float4 L0 = ld_half4(g_xl1h + (long)s0 * C1, c4);
        float p0 = lrelu_dot(L0, R, ea0.x, ea0.y, W0, W1_, A);
#pragma unroll
        for (int o = 16; o > 0; o >>= 1) p0 += __shfl_xor_sync(0xffffffffu, p0, o);
        p0 = __expf(p0);
        den += p0;
        acc.x = fmaf(p0, L0.x, acc.x); acc.y = fmaf(p0, L0.y, acc.y);
        acc.z = fmaf(p0, L0.z, acc.z); acc.w = fmaf(p0, L0.w, acc.w);
    }
    float inv = 1.f / den;
    float4 bb = __ldg((const float4*)b1 + c4);
    float v0 = acc.x * inv + bb.x; v0 = v0 > 0.f ? v0 : (__expf(v0) - 1.f);
    float v1 = acc.y * inv + bb.y; v1 = v1 > 0.f ? v1 : (__expf(v1) - 1.f);
    float v2 = acc.z * inv + bb.z; v2 = v2 > 0.f ? v2 : (__expf(v2) - 1.f);
    float v3 = acc.w * inv + bb.w; v3 = v3 > 0.f ? v3 : (__expf(v3) - 1.f);
    __half2 hA = __floats2half2_rn(v0, v1);
    __half2 hB = __floats2half2_rn(v2, v3);
    uint2 u = make_uint2(*(unsigned*)&hA, *(unsigned*)&hB);
    ((uint2*)(g_h1h + (long)d * C1))[c4] = u;
}

// ---------------- layer-2 SINGLE-PASS fused att+agg+ELU+FC: warp per node ----------------
__global__ void __launch_bounds__(256) k_edge2(const float* __restrict__ W2e,
                                               const float* __restrict__ att2,
                                               const float* __restrict__ b2,
                                               const float* __restrict__ Wfc,
                                               const float* __restrict__ bfc,
                                               float* __restrict__ out, int N) {
    int w = threadIdx.x >> 5, lane = threadIdx.x & 31;
    int node = blockIdx.x * 8 + w;
    if (node >= N) return;
    float4 R  = ((const float4*)(g_xr2 + (long)node * C2))[lane];
    float4 W0 = __ldg((const float4*)W2e + lane);
    float4 W1_ = __ldg((const float4*)(W2e + C2) + lane);
    float4 A  = __ldg((const float4*)att2 + lane);
    int rs = g_rowstart[node], re = g_rowstart[node + 1];
    float den;
    float4 acc;
    {
        float e0 = g_loopea[2 * node], e1 = g_loopea[2 * node + 1];
        float4 L = ld_half4(g_xl2h + (long)node * C2, lane);
        float part = lrelu_dot(L, R, e0, e1, W0, W1_, A);
#pragma unroll
        for (int o = 16; o > 0; o >>= 1) part += __shfl_xor_sync(0xffffffffu, part, o);
        float p = __expf(part);
        den = p;
        acc.x = p * L.x; acc.y = p * L.y; acc.z = p * L.z; acc.w = p * L.w;
    }
    int i = rs;
    for (; i + 4 <= re; i += 4) {
        int s0 = g_esrc[i], s1 = g_esrc[i + 1], s2 = g_esrc[i + 2], s3 = g_esrc[i + 3];
        float2 ea0 = g_eea[i], ea1 = g_eea[i + 1], ea2 = g_eea[i + 2], ea3 = g_eea[i + 3];
        float4 L0 = ld_half4(g_xl2h + (long)s0 * C2, lane);
        float4 L1 = ld_half4(g_xl2h + (long)s1 * C2, lane);
        float4 L2 = ld_half4(g_xl2h + (long)s2 * C2, lane);
        float4 L3 = ld_half4(g_xl2h + (long)s3 * C2, lane);
        float p0 = lrelu_dot(L0, R, ea0.x, ea0.y, W0, W1_, A);
        float p1 = lrelu_dot(L1, R, ea1.x, ea1.y, W0, W1_, A);
        float p2 = lrelu_dot(L2, R, ea2.x, ea2.y, W0, W1_, A);
        float p3 = lrelu_dot(L3, R, ea3.x, ea3.y, W0, W1_, A);
#pragma unroll
        for (int o = 16; o > 0; o >>= 1) {
            p0 += __shfl_xor_sync(0xffffffffu, p0, o);
            p1 += __shfl_xor_sync(0xffffffffu, p1, o);
            p2 += __shfl_xor_sync(0xffffffffu, p2, o);
            p3 += __shfl_xor_sync(0xffffffffu, p3, o);
        }
        p0 = __expf(p0); p1 = __expf(p1); p2 = __expf(p2); p3 = __expf(p3);
        den += (p0 + p1) + (p2 + p3);
        acc.x = fmaf(p0, L0.x, fmaf(p1, L1.x, fmaf(p2, L2.x, fmaf(p3, L3.x, acc.x))));
        acc.y = fmaf(p0, L0.y, fmaf(p1, L1.y, fmaf(p2, L2.y, fmaf(p3, L3.y, acc.y))));
        acc.z = fmaf(p0, L0.z, fmaf(p1, L1.z, fmaf(p2, L2.z, fmaf(p3, L3.z, acc.z))));
        acc.w = fmaf(p0, L0.w, fmaf(p1, L1.w, fmaf(p2, L2.w, fmaf(p3, L3.w, acc.w))));
    }
    for (; i < re; i++) {
        int s0 = g_esrc[i];
        float2 ea0 = g_eea[i];
        float4 L0 = ld_half4(g_xl2h + (long)s0 * C2, lane);
        float p0 = lrelu_dot(L0, R, ea0.x, ea0.y, W0, W1_, A);
#pragma unroll
        for (int o = 16; o > 0; o >>= 1) p0 += __shfl_xor_sync(0xffffffffu, p0, o);
        p0 = __expf(p0);
        den += p0;
        acc.x = fmaf(p0, L0.x, acc.x); acc.y = fmaf(p0, L0.y, acc.y);
        acc.z = fmaf(p0, L0.z, acc.z); acc.w = fmaf(p0, L0.w, acc.w);
    }
    float inv = 1.f / den;
    float4 bb = __ldg((const float4*)b2 + lane);
    float v0 = acc.x * inv + bb.x; v0 = v0 > 0.f ? v0 : (__expf(v0) - 1.f);
    float v1 = acc.y * inv + bb.y; v1 = v1 > 0.f ? v1 : (__expf(v1) - 1.f);
    float v2 = acc.z * inv + bb.z; v2 = v2 > 0.f ? v2 : (__expf(v2) - 1.f);
    float v3 = acc.w * inv + bb.w; v3 = v3 > 0.f ? v3 : (__expf(v3) - 1.f);
    float4 wA = __ldg((const float4*)Wfc + 2 * lane);
    float4 wB = __ldg((const float4*)Wfc + 2 * lane + 1);
    float o0 = v0 * wA.x + v1 * wA.z + v2 * wB.x + v3 * wB.z;
    float o1 = v0 * wA.y + v1 * wA.w + v2 * wB.y + v3 * wB.w;
#pragma unroll
    for (int o = 16; o > 0; o >>= 1) {
        o0 += __shfl_xor_sync(0xffffffffu, o0, o);
        o1 += __shfl_xor_sync(0xffffffffu, o1, o);
    }
    if (lane == 0) {
        out[2 * node]     = o0 + __ldg(bfc);
        out[2 * node + 1] = o1 + __ldg(bfc + 1);
    }
}

// ---------------- launch ----------------
extern "C" void kernel_launch(void* const* d_in, const int* in_sizes, int n_in,
                              void* d_out, int out_size) {
    const float* x    = (const float*)d_in[0];
    const int*   ei   = (const int*)  d_in[1];
    const float* ea   = (const float*)d_in[2];
    const int*   rt   = (const int*)  d_in[3];
    const float* aaem = (const float*)d_in[4];
    const float* W1l  = (const float*)d_in[5];
    const float* W1r  = (const float*)d_in[6];
    const float* W1e  = (const float*)d_in[7];
    const float* att1 = (const float*)d_in[8];
    const float* b1   = (const float*)d_in[9];
    const float* W2l  = (const float*)d_in[10];
    const float* W2r  = (const float*)d_in[11];
    const float* W2e  = (const float*)d_in[12];
    const float* att2 = (const float*)d_in[13];
    const float* b2   = (const float*)d_in[14];
    const float* Wfc  = (const float*)d_in[15];
    const float* bfc  = (const float*)d_in[16];
    float* out = (float*)d_out;

    int N = in_sizes[0] / 5;
    int E = in_sizes[1] / 2;
    if (N > MAXN) N = MAXN;
    if (E > MAXE) E = MAXE;
    const int* src = ei;
    const int* dst = ei + E;
    int NP_BLK = (N + 63) / 64;
    int nb = (N + 1023) / 1024;

    // lazily-created side stream + fork/join events (host resources, no device mem)
    static bool s_init = false;
    static cudaStream_t sB;
    static cudaEvent_t evF, evJ;
    if (!s_init) {
        cudaStreamCreateWithFlags(&sB, cudaStreamNonBlocking);
        cudaEventCreateWithFlags(&evF, cudaEventDisableTiming);
        cudaEventCreateWithFlags(&evJ, cudaEventDisableTiming);
        s_init = true;
    }

    // fork: preprocessing chain (edge data) on sB, concurrent with gemm1 (feature data)
    cudaEventRecord(evF, 0);
    cudaStreamWaitEvent(sB, evF, 0);
    k_init<<<(N + 255) / 256, 256, 0, sB>>>(N);
    k_deg<<<(E + 255) / 256, 256, 0, sB>>>(dst, ea, E);
    k_scan1<<<nb, 1024, 0, sB>>>(N);
    k_scan3<<<(N + 255) / 256, 256, 0, sB>>>(N, nb);
    k_scatter<<<(E + 255) / 256, 256, 0, sB>>>(src, dst, ea, E);
    cudaEventRecord(evJ, sB);

    k_gemm1<<<dim3(NP_BLK, 4, 2), 256>>>(x, rt, aaem, W1l, W1r, N);

    // join: edge1 needs both gemm1 outputs and CSR/loopea
    cudaStreamWaitEvent(0, evJ, 0);
    k_edge1<<<N, 128>>>(W1e, att1, b1, N);

    k_gemm2<<<dim3(NP_BLK, 1, 2), 256>>>(W2l, W2r, N);
    k_edge2<<<(N + 7) / 8, 256>>>(W2e, att2, b2, Wfc, bfc, out, N);
}

// round 12
// speedup vs baseline: 3.0424x; 1.1806x over previous
#include <cuda_runtime.h>
#include <cuda_fp16.h>
#include <mma.h>
#include <math.h>
#include <float.h>

using namespace nvcuda;

#define MAXN 20000
#define MAXNP 20032
#define MAXE 150000
#define C1 512
#define H1 4
#define C2 128

// ---------------- scratch ----------------
static __device__ __half g_xl1h[MAXNP * C1];   // gather-side features, fp16
static __device__ __half g_xr1h[MAXNP * C1];   // dst-side features, fp16
static __device__ __half g_h1h[MAXNP * C1];    // layer-1 output, fp16 (gemm2 A operand)
static __device__ __half g_xl2h[MAXNP * C2];
static __device__ __half g_xr2h[MAXNP * C2];
static __device__ float  g_easum[MAXN * 2];
static __device__ float  g_loopea[MAXN * 2];
static __device__ int    g_deg[MAXN];
static __device__ int    g_rowstart[MAXN + 1];
static __device__ int    g_cursor[MAXN];
static __device__ int    g_esrc[MAXE];         // src permuted into CSR order
static __device__ float2 g_eea[MAXE];          // edge_attr permuted into CSR order
static __device__ int    g_blocksum[32];

// ---------------- per-node init ----------------
__global__ void k_init(int N) {
    int i = blockIdx.x * blockDim.x + threadIdx.x;
    if (i >= N) return;
    g_deg[i] = 0;
    g_cursor[i] = 0;
    g_easum[2 * i] = 0.f;
    g_easum[2 * i + 1] = 0.f;
}

// ---------------- degree + edge-attr sums ----------------
__global__ void k_deg(const int* __restrict__ dst, const float* __restrict__ ea, int E) {
    int e = blockIdx.x * blockDim.x + threadIdx.x;
    if (e >= E) return;
    int d = dst[e];
    float2 a = ((const float2*)ea)[e];
    atomicAdd(&g_deg[d], 1);
    atomicAdd(&g_easum[2 * d], a.x);
    atomicAdd(&g_easum[2 * d + 1], a.y);
}

// ---------------- parallel scan ----------------
__global__ void k_scan1(int N) {
    __shared__ int sm[1024];
    int i = blockIdx.x * 1024 + threadIdx.x;
    int v = (i < N) ? g_deg[i] : 0;
    sm[threadIdx.x] = v;
    __syncthreads();
    for (int o = 1; o < 1024; o <<= 1) {
        int t = (threadIdx.x >= o) ? sm[threadIdx.x - o] : 0;
        __syncthreads();
        sm[threadIdx.x] += t;
        __syncthreads();
    }
    if (i < N) g_rowstart[i] = sm[threadIdx.x] - v;
    if (threadIdx.x == 1023) g_blocksum[blockIdx.x] = sm[1023];
}
__global__ void k_scan3(int N, int nb) {
    __shared__ int soff[32];
    int t = threadIdx.x;
    if (t < 32) {
        int v = (t < nb) ? g_blocksum[t] : 0;
        int s = v;
#pragma unroll
        for (int o = 1; o < 32; o <<= 1) {
            int u = __shfl_up_sync(0xffffffffu, s, o);
            if (t >= o) s += u;
        }
        soff[t] = s - v;
    }
    __syncthreads();
    int i = blockIdx.x * blockDim.x + t;
    if (i < N) {
        g_rowstart[i] += soff[i >> 10];
        int dg = g_deg[i];
        float fd = (dg < 1) ? 1.f : (float)dg;
        g_loopea[2 * i]     = g_easum[2 * i] / fd;
        g_loopea[2 * i + 1] = g_easum[2 * i + 1] / fd;
    }
    if (i == 0) g_rowstart[N] = soff[31];
}

__global__ void k_scatter(const int* __restrict__ src, const int* __restrict__ dst,
                          const float* __restrict__ ea, int E) {
    int e = blockIdx.x * blockDim.x + threadIdx.x;
    if (e >= E) return;
    int d = dst[e];
    int pos = g_rowstart[d] + atomicAdd(&g_cursor[d], 1);
    g_esrc[pos] = src[e];
    g_eea[pos] = ((const float2*)ea)[e];
}

// ---- epilogue helper: warp writes one 16x16 fp32 tile (ldm=16) as fp16 (16B stores) ----
__device__ __forceinline__ void tile_to_half(const float* st, __half* gbase,
                                             long grow0, int gcol0, int ldg_, int lane) {
    int row = lane >> 1, colh = (lane & 1) * 8;
    const float* sp = st + row * 16 + colh;
    __half2 h0 = __floats2half2_rn(sp[0], sp[1]);
    __half2 h1 = __floats2half2_rn(sp[2], sp[3]);
    __half2 h2 = __floats2half2_rn(sp[4], sp[5]);
    __half2 h3 = __floats2half2_rn(sp[6], sp[7]);
    uint4 u = make_uint4(*(unsigned*)&h0, *(unsigned*)&h1, *(unsigned*)&h2, *(unsigned*)&h3);
    *(uint4*)(gbase + (grow0 + row) * ldg_ + gcol0 + colh) = u;
}

// ---------------- layer-1 GEMM (fp16 WMMA m16n16k16): concat(x, aa_emb[rt]) @ [48,512] ----------------
// h0 concat fused into A-tile load; K padded 37->48. z=0 -> xl1h, z=1 -> xr1h
__global__ void __launch_bounds__(256) k_gemm1(const float* __restrict__ x,
                                               const int* __restrict__ rt,
                                               const float* __restrict__ aaemb,
                                               const float* __restrict__ Wl,
                                               const float* __restrict__ Wr, int N) {
    const float* W = blockIdx.z ? Wr : Wl;
    __half* outh = blockIdx.z ? g_xr1h : g_xl1h;
    __shared__ __half Ah[64 * 56];       // stride 56 halves = 112B (16B-multiple)
    __shared__ __half Bh[48 * 136];      // stride 136 halves = 272B
    __shared__ float stg[8 * 256];
    int tid = threadIdx.x;
    int n0 = blockIdx.x * 64;
    int col0 = blockIdx.y * 128;
    for (int idx = tid; idx < 64 * 48; idx += 256) {
        int r = idx / 48, c = idx - r * 48;
        int n = n0 + r;
        float v = 0.f;
        if (n < N) {
            if (c < 5) v = x[n * 5 + c];
            else if (c < 37) v = aaemb[rt[n] * 32 + (c - 5)];
        }
        Ah[r * 56 + c] = __float2half(v);
    }
    for (int idx = tid; idx < 48 * 128; idx += 256) {
        int r = idx >> 7, c = idx & 127;
        float v = (r < 37) ? W[r * C1 + col0 + c] : 0.f;
        Bh[r * 136 + c] = __float2half(v);
    }
    __syncthreads();
    int wid = tid >> 5, lane = tid & 31;
    int wr = wid & 1, wc = wid >> 1;
    wmma::fragment<wmma::accumulator, 16, 16, 16, float> acc[2][2];
#pragma unroll
    for (int i = 0; i < 2; i++)
#pragma unroll
        for (int j = 0; j < 2; j++) wmma::fill_fragment(acc[i][j], 0.f);
#pragma unroll
    for (int kk = 0; kk < 48; kk += 16) {
        wmma::fragment<wmma::matrix_a, 16, 16, 16, __half, wmma::row_major> a[2];
        wmma::fragment<wmma::matrix_b, 16, 16, 16, __half, wmma::row_major> b[2];
#pragma unroll
        for (int i = 0; i < 2; i++)
            wmma::load_matrix_sync(a[i], &Ah[(wr * 32 + i * 16) * 56 + kk], 56);
#pragma unroll
        for (int j = 0; j < 2; j++)
            wmma::load_matrix_sync(b[j], &Bh[kk * 136 + wc * 32 + j * 16], 136);
#pragma unroll
        for (int i = 0; i < 2; i++)
#pragma unroll
            for (int j = 0; j < 2; j++)
                wmma::mma_sync(acc[i][j], a[i], b[j], acc[i][j]);
    }
    float* st = stg + wid * 256;
#pragma unroll
    for (int i = 0; i < 2; i++)
#pragma unroll
        for (int j = 0; j < 2; j++) {
            wmma::store_matrix_sync(st, acc[i][j], 16, wmma::mem_row_major);
            __syncwarp();
            tile_to_half(st, outh, n0 + wr * 32 + i * 16,
                         col0 + wc * 32 + j * 16, C1, lane);
            __syncwarp();
        }
}

// ---------------- layer-2 GEMM (fp16 WMMA m16n16k16): h1h[NP,512] @ [512,128] ----------------
__global__ void __launch_bounds__(256) k_gemm2(const float* __restrict__ Wl,
                                               const float* __restrict__ Wr, int N) {
    const float* W = blockIdx.z ? Wr : Wl;
    __half* outh = blockIdx.z ? g_xr2h : g_xl2h;
    __shared__ __half Ah[64 * 40];       // stride 40 halves = 80B
    __shared__ __half Bh[32 * 136];
    __shared__ float stg[8 * 256];
    int tid = threadIdx.x;
    int n0 = blockIdx.x * 64;
    int wid = tid >> 5, lane = tid & 31;
    int wr = wid & 1, wc = wid >> 1;
    wmma::fragment<wmma::accumulator, 16, 16, 16, float> acc[2][2];
#pragma unroll
    for (int i = 0; i < 2; i++)
#pragma unroll
        for (int j = 0; j < 2; j++) wmma::fill_fragment(acc[i][j], 0.f);
    for (int k0 = 0; k0 < C1; k0 += 32) {
        {   // A: 64x32 halves, one uint4 (8 halves) per thread
            int r = tid >> 2, g = (tid & 3) * 8;
            uint4 u = make_uint4(0, 0, 0, 0);
            if (n0 + r < N)
                u = *(const uint4*)(g_h1h + (long)(n0 + r) * C1 + k0 + g);
            *(uint4*)(Ah + r * 40 + g) = u;
        }
        for (int idx = tid; idx < 32 * 128; idx += 256) {
            int r = idx >> 7, c = idx & 127;
            Bh[r * 136 + c] = __float2half(W[(k0 + r) * C2 + c]);
        }
        __syncthreads();
#pragma unroll
        for (int kk = 0; kk < 32; kk += 16) {
            wmma::fragment<wmma::matrix_a, 16, 16, 16, __half, wmma::row_major> a[2];
            wmma::fragment<wmma::matrix_b, 16, 16, 16, __half, wmma::row_major> b[2];
#pragma unroll
            for (int i = 0; i < 2; i++)
                wmma::load_matrix_sync(a[i], &Ah[(wr * 32 + i * 16) * 40 + kk], 40);
#pragma unroll
            for (int j = 0; j < 2; j++)
                wmma::load_matrix_sync(b[j], &Bh[kk * 136 + wc * 32 + j * 16], 136);
#pragma unroll
            for (int i = 0; i < 2; i++)
#pragma unroll
                for (int j = 0; j < 2; j++)
                    wmma::mma_sync(acc[i][j], a[i], b[j], acc[i][j]);
        }
        __syncthreads();
    }
    float* st = stg + wid * 256;
#pragma unroll
    for (int i = 0; i < 2; i++)
#pragma unroll
        for (int j = 0; j < 2; j++) {
            wmma::store_matrix_sync(st, acc[i][j], 16, wmma::mem_row_major);
            __syncwarp();
            tile_to_half(st, outh, n0 + wr * 32 + i * 16,
                         wc * 32 + j * 16, C2, lane);
            __syncwarp();
        }
}

// ---- helpers ----
__device__ __forceinline__ float4 ld_half4(const __half* base, int idx4) {
    uint2 u = __ldg((const uint2*)base + idx4);
    __half2 ha = *(__half2*)&u.x, hb = *(__half2*)&u.y;
    float2 fa = __half22float2(ha), fb = __half22float2(hb);
    return make_float4(fa.x, fa.y, fb.x, fb.y);
}
__device__ __forceinline__ float lrelu_dot(float4 L, float4 R, float e0, float e1,
                                           float4 W0, float4 W1_, float4 A) {
    float zx = L.x + R.x + e0 * W0.x + e1 * W1_.x; zx = zx > 0.f ? zx : 0.2f * zx;
    float zy = L.y + R.y + e0 * W0.y + e1 * W1_.y; zy = zy > 0.f ? zy : 0.2f * zy;
    float zz = L.z + R.z + e0 * W0.z + e1 * W1_.z; zz = zz > 0.f ? zz : 0.2f * zz;
    float zw = L.w + R.w + e0 * W0.w + e1 * W1_.w; zw = zw > 0.f ? zw : 0.2f * zw;
    return A.x * zx + A.y * zy + A.z * zz + A.w * zw;
}

// ---------------- layer-1 SINGLE-PASS fused attention+aggregation ----------------
__global__ void __launch_bounds__(128) k_edge1(const float* __restrict__ W1e,
                                               const float* __restrict__ att,
                                               const float* __restrict__ b1, int N) {
    int d = blockIdx.x;
    int lane = threadIdx.x & 31, h = threadIdx.x >> 5;
    int c4 = h * 32 + lane;
    float4 R  = ld_half4(g_xr1h + (long)d * C1, c4);
    float4 W0 = __ldg((const float4*)W1e + c4);
    float4 W1_ = __ldg((const float4*)(W1e + C1) + c4);
    float4 A  = __ldg((const float4*)att + c4);
    int rs = g_rowstart[d], re = g_rowstart[d + 1];
    float den;
    float4 acc;
    {   // self loop
        float e0 = g_loopea[2 * d], e1 = g_loopea[2 * d + 1];
        float4 L = ld_half4(g_xl1h + (long)d * C1, c4);
        float part = lrelu_dot(L, R, e0, e1, W0, W1_, A);
#pragma unroll
        for (int o = 16; o > 0; o >>= 1) part += __shfl_xor_sync(0xffffffffu, part, o);
        float p = __expf(part);
        den = p;
        acc.x = p * L.x; acc.y = p * L.y; acc.z = p * L.z; acc.w = p * L.w;
    }
    int i = rs;
    for (; i + 4 <= re; i += 4) {
        int s0 = __ldg(g_esrc + i), s1 = __ldg(g_esrc + i + 1);
        int s2 = __ldg(g_esrc + i + 2), s3 = __ldg(g_esrc + i + 3);
        float2 ea0 = __ldg(g_eea + i), ea1 = __ldg(g_eea + i + 1);
        float2 ea2 = __ldg(g_eea + i + 2), ea3 = __ldg(g_eea + i + 3);
        float4 L0 = ld_half4(g_xl1h + (long)s0 * C1, c4);
        float4 L1 = ld_half4(g_xl1h + (long)s1 * C1, c4);
        float4 L2 = ld_half4(g_xl1h + (long)s2 * C1, c4);
        float4 L3 = ld_half4(g_xl1h + (long)s3 * C1, c4);
        float p0 = lrelu_dot(L0, R, ea0.x, ea0.y, W0, W1_, A);
        float p1 = lrelu_dot(L1, R, ea1.x, ea1.y, W0, W1_, A);
        float p2 = lrelu_dot(L2, R, ea2.x, ea2.y, W0, W1_, A);
        float p3 = lrelu_dot(L3, R, ea3.x, ea3.y, W0, W1_, A);
#pragma unroll
        for (int o = 16; o > 0; o >>= 1) {
            p0 += __shfl_xor_sync(0xffffffffu, p0, o);
            p1 += __shfl_xor_sync(0xffffffffu, p1, o);
            p2 += __shfl_xor_sync(0xffffffffu, p2, o);
            p3 += __shfl_xor_sync(0xffffffffu, p3, o);
        }
        p0 = __expf(p0); p1 = __expf(p1); p2 = __expf(p2); p3 = __expf(p3);
        den += (p0 + p1) + (p2 + p3);
        acc.x = fmaf(p0, L0.x, fmaf(p1, L1.x, fmaf(p2, L2.x, fmaf(p3, L3.x, acc.x))));
        acc.y = fmaf(p0, L0.y, fmaf(p1, L1.y, fmaf(p2, L2.y, fmaf(p3, L3.y, acc.y))));
        acc.z = fmaf(p0, L0.z, fmaf(p1, L1.z, fmaf(p2, L2.z, fmaf(p3, L3.z, acc.z))));
        acc.w = fmaf(p0, L0.w, fmaf(p1, L1.w, fmaf(p2, L2.w, fmaf(p3, L3.w, acc.w))));
    }
    for (; i < re; i++) {
        int s0 = __ldg(g_esrc + i);
        float2 ea0 = __ldg(g_eea + i);
        float4 L0 = ld_half4(g_xl1h + (long)s0 * C1, c4);
        float p0 = lrelu_dot(L0, R, ea0.x, ea0.y, W0, W1_, A);
#pragma unroll
        for (int o = 16; o > 0; o >>= 1) p0 += __shfl_xor_sync(0xffffffffu, p0, o);
        p0 = __expf(p0);
        den += p0;
        acc.x = fmaf(p0, L0.x, acc.x); acc.y = fmaf(p0, L0.y, acc.y);
        acc.z = fmaf(p0, L0.z, acc.z); acc.w = fmaf(p0, L0.w, acc.w);
    }
    float inv = 1.f / den;
    float4 bb = __ldg((const float4*)b1 + c4);
    float v0 = acc.x * inv + bb.x; v0 = v0 > 0.f ? v0 : (__expf(v0) - 1.f);
    float v1 = acc.y * inv + bb.y; v1 = v1 > 0.f ? v1 : (__expf(v1) - 1.f);
    float v2 = acc.z * inv + bb.z; v2 = v2 > 0.f ? v2 : (__expf(v2) - 1.f);
    float v3 = acc.w * inv + bb.w; v3 = v3 > 0.f ? v3 : (__expf(v3) - 1.f);
    __half2 hA = __floats2half2_rn(v0, v1);
    __half2 hB = __floats2half2_rn(v2, v3);
    uint2 u = make_uint2(*(unsigned*)&hA, *(unsigned*)&hB);
    ((uint2*)(g_h1h + (long)d * C1))[c4] = u;
}

// ---------------- layer-2 SINGLE-PASS fused att+agg+ELU+FC: warp per node ----------------
__global__ void __launch_bounds__(256) k_edge2(const float* __restrict__ W2e,
                                               const float* __restrict__ att2,
                                               const float* __restrict__ b2,
                                               const float* __restrict__ Wfc,
                                               const float* __restrict__ bfc,
                                               float* __restrict__ out, int N) {
    int w = threadIdx.x >> 5, lane = threadIdx.x & 31;
    int node = blockIdx.x * 8 + w;
    if (node >= N) return;
    float4 R  = ld_half4(g_xr2h + (long)node * C2, lane);
    float4 W0 = __ldg((const float4*)W2e + lane);
    float4 W1_ = __ldg((const float4*)(W2e + C2) + lane);
    float4 A  = __ldg((const float4*)att2 + lane);
    int rs = g_rowstart[node], re = g_rowstart[node + 1];
    float den;
    float4 acc;
    {
        float e0 = g_loopea[2 * node], e1 = g_loopea[2 * node + 1];
        float4 L = ld_half4(g_xl2h + (long)node * C2, lane);
        float part = lrelu_dot(L, R, e0, e1, W0, W1_, A);
#pragma unroll
        for (int o = 16; o > 0; o >>= 1) part += __shfl_xor_sync(0xffffffffu, part, o);
        float p = __expf(part);
        den = p;
        acc.x = p * L.x; acc.y = p * L.y; acc.z = p * L.z; acc.w = p * L.w;
    }
    int i = rs;
    for (; i + 4 <= re; i += 4) {
        int s0 = __ldg(g_esrc + i), s1 = __ldg(g_esrc + i + 1);
        int s2 = __ldg(g_esrc + i + 2), s3 = __ldg(g_esrc + i + 3);
        float2 ea0 = __ldg(g_eea + i), ea1 = __ldg(g_eea + i + 1);
        float2 ea2 = __ldg(g_eea + i + 2), ea3 = __ldg(g_eea + i + 3);
        float4 L0 = ld_half4(g_xl2h + (long)s0 * C2, lane);
        float4 L1 = ld_half4(g_xl2h + (long)s1 * C2, lane);
        float4 L2 = ld_half4(g_xl2h + (long)s2 * C2, lane);
        float4 L3 = ld_half4(g_xl2h + (long)s3 * C2, lane);
        float p0 = lrelu_dot(L0, R, ea0.x, ea0.y, W0, W1_, A);
        float p1 = lrelu_dot(L1, R, ea1.x, ea1.y, W0, W1_, A);
        float p2 = lrelu_dot(L2, R, ea2.x, ea2.y, W0, W1_, A);
        float p3 = lrelu_dot(L3, R, ea3.x, ea3.y, W0, W1_, A);
#pragma unroll
        for (int o = 16; o > 0; o >>= 1) {
            p0 += __shfl_xor_sync(0xffffffffu, p0, o);
            p1 += __shfl_xor_sync(0xffffffffu, p1, o);
            p2 += __shfl_xor_sync(0xffffffffu, p2, o);
            p3 += __shfl_xor_sync(0xffffffffu, p3, o);
        }
        p0 = __expf(p0); p1 = __expf(p1); p2 = __expf(p2); p3 = __expf(p3);
        den += (p0 + p1) + (p2 + p3);
        acc.x = fmaf(p0, L0.x, fmaf(p1, L1.x, fmaf(p2, L2.x, fmaf(p3, L3.x, acc.x))));
        acc.y = fmaf(p0, L0.y, fmaf(p1, L1.y, fmaf(p2, L2.y, fmaf(p3, L3.y, acc.y))));
        acc.z = fmaf(p0, L0.z, fmaf(p1, L1.z, fmaf(p2, L2.z, fmaf(p3, L3.z, acc.z))));
        acc.w = fmaf(p0, L0.w, fmaf(p1, L1.w, fmaf(p2, L2.w, fmaf(p3, L3.w, acc.w))));
    }
    for (; i < re; i++) {
        int s0 = __ldg(g_esrc + i);
        float2 ea0 = __ldg(g_eea + i);
        float4 L0 = ld_half4(g_xl2h + (long)s0 * C2, lane);
        float p0 = lrelu_dot(L0, R, ea0.x, ea0.y, W0, W1_, A);
#pragma unroll
        for (int o = 16; o > 0; o >>= 1) p0 += __shfl_xor_sync(0xffffffffu, p0, o);
        p0 = __expf(p0);
        den += p0;
        acc.x = fmaf(p0, L0.x, acc.x); acc.y = fmaf(p0, L0.y, acc.y);
        acc.z = fmaf(p0, L0.z, acc.z); acc.w = fmaf(p0, L0.w, acc.w);
    }
    float inv = 1.f / den;
    float4 bb = __ldg((const float4*)b2 + lane);
    float v0 = acc.x * inv + bb.x; v0 = v0 > 0.f ? v0 : (__expf(v0) - 1.f);
    float v1 = acc.y * inv + bb.y; v1 = v1 > 0.f ? v1 : (__expf(v1) - 1.f);
    float v2 = acc.z * inv + bb.z; v2 = v2 > 0.f ? v2 : (__expf(v2) - 1.f);
    float v3 = acc.w * inv + bb.w; v3 = v3 > 0.f ? v3 : (__expf(v3) - 1.f);
    float4 wA = __ldg((const float4*)Wfc + 2 * lane);
    float4 wB = __ldg((const float4*)Wfc + 2 * lane + 1);
    float o0 = v0 * wA.x + v1 * wA.z + v2 * wB.x + v3 * wB.z;
    float o1 = v0 * wA.y + v1 * wA.w + v2 * wB.y + v3 * wB.w;
#pragma unroll
    for (int o = 16; o > 0; o >>= 1) {
        o0 += __shfl_xor_sync(0xffffffffu, o0, o);
        o1 += __shfl_xor_sync(0xffffffffu, o1, o);
    }
    if (lane == 0) {
        out[2 * node]     = o0 + __ldg(bfc);
        out[2 * node + 1] = o1 + __ldg(bfc + 1);
    }
}

// ---------------- launch ----------------
extern "C" void kernel_launch(void* const* d_in, const int* in_sizes, int n_in,
                              void* d_out, int out_size) {
    const float* x    = (const float*)d_in[0];
    const int*   ei   = (const int*)  d_in[1];
    const float* ea   = (const float*)d_in[2];
    const int*   rt   = (const int*)  d_in[3];
    const float* aaem = (const float*)d_in[4];
    const float* W1l  = (const float*)d_in[5];
    const float* W1r  = (const float*)d_in[6];
    const float* W1e  = (const float*)d_in[7];
    const float* att1 = (const float*)d_in[8];
    const float* b1   = (const float*)d_in[9];
    const float* W2l  = (const float*)d_in[10];
    const float* W2r  = (const float*)d_in[11];
    const float* W2e  = (const float*)d_in[12];
    const float* att2 = (const float*)d_in[13];
    const float* b2   = (const float*)d_in[14];
    const float* Wfc  = (const float*)d_in[15];
    const float* bfc  = (const float*)d_in[16];
    float* out = (float*)d_out;

    int N = in_sizes[0] / 5;
    int E = in_sizes[1] / 2;
    if (N > MAXN) N = MAXN;
    if (E > MAXE) E = MAXE;
    const int* src = ei;
    const int* dst = ei + E;
    int NP_BLK = (N + 63) / 64;
    int nb = (N + 1023) / 1024;

    // lazily-created side stream + fork/join events (host resources, no device mem)
    static bool s_init = false;
    static cudaStream_t sB;
    static cudaEvent_t evF, evJ;
    if (!s_init) {
        cudaStreamCreateWithFlags(&sB, cudaStreamNonBlocking);
        cudaEventCreateWithFlags(&evF, cudaEventDisableTiming);
        cudaEventCreateWithFlags(&evJ, cudaEventDisableTiming);
        s_init = true;
    }

    // fork: preprocessing chain (edge data) on sB, concurrent with gemm1 (feature data)
    cudaEventRecord(evF, 0);
    cudaStreamWaitEvent(sB, evF, 0);
    k_init<<<(N + 255) / 256, 256, 0, sB>>>(N);
    k_deg<<<(E + 255) / 256, 256, 0, sB>>>(dst, ea, E);
    k_scan1<<<nb, 1024, 0, sB>>>(N);
    k_scan3<<<(N + 255) / 256, 256, 0, sB>>>(N, nb);
    k_scatter<<<(E + 255) / 256, 256, 0, sB>>>(src, dst, ea, E);
    cudaEventRecord(evJ, sB);

    k_gemm1<<<dim3(NP_BLK, 4, 2), 256>>>(x, rt, aaem, W1l, W1r, N);

    // join: edge1 needs both gemm1 outputs and CSR/loopea
    cudaStreamWaitEvent(0, evJ, 0);
    k_edge1<<<N, 128>>>(W1e, att1, b1, N);

    k_gemm2<<<dim3(NP_BLK, 1, 2), 256>>>(W2l, W2r, N);
    k_edge2<<<(N + 7) / 8, 256>>>(W2e, att2, b2, Wfc, bfc, out, N);
}